// round 10
// baseline (speedup 1.0000x reference)
#include <cuda_runtime.h>
#include <cuda_bf16.h>
#include <math.h>
#include <stdint.h>

#define TB 2
#define TT 2048
#define TD 1024
#define NQH 16
#define NKH 8
#define HD 128
#define BT (TB*TT)          // 4096
#define QKV_LD 4096
#define ATT_LD 2048
#define EPSV 1e-6f
#define SCALEV 0.08838834764831845f
#define LOG2_THETA 19.9315685693241740f
#define MASKV (-3.0e38f)
#define NEGI (-1e30f)

typedef __nv_bfloat16 bf16;
typedef __nv_bfloat162 bf162;

// Scratch (device globals; no runtime allocation)
__device__ bf16 g_xh[(size_t)BT*TD],     g_xl[(size_t)BT*TD];
__device__ bf16 g_wh[(size_t)TD*QKV_LD], g_wl[(size_t)TD*QKV_LD];
__device__ bf16 g_qh[(size_t)BT*QKV_LD], g_ql[(size_t)BT*QKV_LD];
__device__ bf16 g_ah[(size_t)BT*ATT_LD], g_al[(size_t)BT*ATT_LD];
__device__ bf16 g_oh[(size_t)ATT_LD*TD], g_ol[(size_t)ATT_LD*TD];
__device__ float2 g_rope[(size_t)BT*64];
__device__ int  g_pos[BT];

// ---------------------------------------------------------------------------
// helpers
// ---------------------------------------------------------------------------
__device__ __forceinline__ uint32_t s2u(const void* p){
    return (uint32_t)__cvta_generic_to_shared(p);
}
__device__ __forceinline__ void ldm4(uint32_t* r, uint32_t a){
    asm volatile("ldmatrix.sync.aligned.m8n8.x4.shared.b16 {%0,%1,%2,%3}, [%4];"
        : "=r"(r[0]),"=r"(r[1]),"=r"(r[2]),"=r"(r[3]) : "r"(a));
}
__device__ __forceinline__ void ldm4t(uint32_t* r, uint32_t a){
    asm volatile("ldmatrix.sync.aligned.m8n8.x4.trans.shared.b16 {%0,%1,%2,%3}, [%4];"
        : "=r"(r[0]),"=r"(r[1]),"=r"(r[2]),"=r"(r[3]) : "r"(a));
}
__device__ __forceinline__ void mma16816(float* c, const uint32_t* a, const uint32_t* b){
    asm volatile("mma.sync.aligned.m16n8k16.row.col.f32.bf16.bf16.f32 "
        "{%0,%1,%2,%3}, {%4,%5,%6,%7}, {%8,%9}, {%0,%1,%2,%3};"
        : "+f"(c[0]),"+f"(c[1]),"+f"(c[2]),"+f"(c[3])
        : "r"(a[0]),"r"(a[1]),"r"(a[2]),"r"(a[3]),"r"(b[0]),"r"(b[1]));
}
__device__ __forceinline__ void hl_pack(float x, float y, uint32_t& h, uint32_t& l){
    bf16 hx = __float2bfloat16(x), hy = __float2bfloat16(y);
    bf162 th = __halves2bfloat162(hx, hy);
    h = *reinterpret_cast<uint32_t*>(&th);
    bf162 tl = __floats2bfloat162_rn(x - __bfloat162float(hx), y - __bfloat162float(hy));
    l = *reinterpret_cast<uint32_t*>(&tl);
}
__device__ __forceinline__ void hl_split1(float x, bf16& h, bf16& l){
    h = __float2bfloat16(x);
    l = __float2bfloat16(x - __bfloat162float(h));
}

// ---------------------------------------------------------------------------
// Kernel: positions from segment ids
// ---------------------------------------------------------------------------
__global__ void pos_kernel(const int* __restrict__ seg, int* __restrict__ pos) {
    const int b = blockIdx.x;
    const int tid = threadIdx.x;
    __shared__ int red[256];
    int mx = -2147483647 - 1;
    for (int t = tid; t < TT; t += 256) mx = max(mx, seg[b*TT + t]);
    red[tid] = mx; __syncthreads();
    for (int s = 128; s > 0; s >>= 1) {
        if (tid < s) red[tid] = max(red[tid], red[tid + s]);
        __syncthreads();
    }
    const int gmax = red[0];
    __syncthreads();
    int idx = TT;
    for (int t = tid; t < TT; t += 256)
        if (seg[b*TT + t] == gmax && t < idx) idx = t;
    red[tid] = idx; __syncthreads();
    for (int s = 128; s > 0; s >>= 1) {
        if (tid < s) red[tid] = min(red[tid], red[tid + s]);
        __syncthreads();
    }
    const int off = red[0];
    for (int t = tid; t < TT; t += 256) {
        int sv = seg[b*TT + t];
        pos[b*TT + t] = (sv != 0) ? (t - off) : (1 << 30);
    }
}

// ---------------------------------------------------------------------------
// Kernel: rope table  rope[bt][j] = (sin, cos)(pos[bt] * theta^-(j/64))
// ---------------------------------------------------------------------------
__global__ void rope_kernel(const int* __restrict__ pos, float2* __restrict__ rope){
    int idx = blockIdx.x*blockDim.x + threadIdx.x;   // BT*64 total
    int bt = idx >> 6, j = idx & 63;
    float inv_freq = exp2f(-(float)j * (LOG2_THETA / 64.f));
    float ang = (float)pos[bt] * inv_freq;
    float s, c;
    sincosf(ang, &s, &c);
    rope[idx] = make_float2(s, c);
}

// ---------------------------------------------------------------------------
// Kernel: fp32 -> bf16 hi/lo split
// ---------------------------------------------------------------------------
__global__ void split_kernel(const float* __restrict__ src, bf16* __restrict__ dh,
                             bf16* __restrict__ dl, int rows, int cols,
                             int sld, int dld, int doff)
{
    const int c4 = cols >> 2;
    const int total = rows * c4;
    for (int i = blockIdx.x*blockDim.x + threadIdx.x; i < total; i += gridDim.x*blockDim.x) {
        int r = i / c4;
        int c = (i - r*c4) * 4;
        float4 v = *(const float4*)&src[(size_t)r*sld + c];
        bf16 h0,h1,h2,h3,l0,l1,l2,l3;
        hl_split1(v.x,h0,l0); hl_split1(v.y,h1,l1);
        hl_split1(v.z,h2,l2); hl_split1(v.w,h3,l3);
        size_t o = (size_t)r*dld + doff + c;
        *(bf162*)&dh[o]   = __halves2bfloat162(h0,h1);
        *(bf162*)&dh[o+2] = __halves2bfloat162(h2,h3);
        *(bf162*)&dl[o]   = __halves2bfloat162(l0,l1);
        *(bf162*)&dl[o+2] = __halves2bfloat162(l2,l3);
    }
}

// ---------------------------------------------------------------------------
// bf16x3 GEMM mainloop (proven): 128x128 block, 8 warps, K-step 32, dbl-buffered
// ---------------------------------------------------------------------------
#define GA_STR 40
#define GB_STR 136
#define G_ASZ (128*GA_STR)
#define G_BSZ (32*GB_STR)
#define G_BUF (2*G_ASZ + 2*G_BSZ)
#define GEMM_SMEM (2*G_BUF*2)

#define GEMM3_MAINLOOP \
    extern __shared__ bf16 sm[]; \
    const int tid = threadIdx.x, lane = tid&31, warp = tid>>5; \
    const int wm = warp&1, wn = warp>>1; \
    const int m0 = blockIdx.y*128, n0 = blockIdx.x*128; \
    float acc[4][4][4]; \
    _Pragma("unroll") for (int i=0;i<4;i++) \
    _Pragma("unroll") for (int j=0;j<4;j++) \
    _Pragma("unroll") for (int q=0;q<4;q++) acc[i][j][q]=0.f; \
    uint4 ra_h[2], ra_l[2], rb_h[2], rb_l[2]; \
    auto loadT = [&](int k0){ \
        _Pragma("unroll") for (int i=0;i<2;i++){ \
            int f = tid + i*256; \
            int r = f>>2, k8 = (f&3)*8; \
            size_t ao = (size_t)(m0+r)*lda + k0 + k8; \
            ra_h[i] = *(const uint4*)(Ah+ao); \
            ra_l[i] = *(const uint4*)(Al+ao); \
            int kr = f>>4, n8 = (f&15)*8; \
            size_t bo = (size_t)(k0+kr)*ldb + n0 + n8; \
            rb_h[i] = *(const uint4*)(Bh+bo); \
            rb_l[i] = *(const uint4*)(Bl+bo); \
        } \
    }; \
    auto storeT = [&](int buf){ \
        bf16* base = sm + buf*G_BUF; \
        _Pragma("unroll") for (int i=0;i<2;i++){ \
            int f = tid + i*256; \
            int r = f>>2, k8 = (f&3)*8; \
            *(uint4*)(base + r*GA_STR + k8) = ra_h[i]; \
            *(uint4*)(base + G_ASZ + r*GA_STR + k8) = ra_l[i]; \
            int kr = f>>4, n8 = (f&15)*8; \
            *(uint4*)(base + 2*G_ASZ + kr*GB_STR + n8) = rb_h[i]; \
            *(uint4*)(base + 2*G_ASZ + G_BSZ + kr*GB_STR + n8) = rb_l[i]; \
        } \
    }; \
    const int nk = Kd >> 5; \
    loadT(0); storeT(0); __syncthreads(); \
    int cur = 0; \
    const int ar = lane&15, ac8 = (lane>>4)*8; \
    for (int t=0; t<nk; t++){ \
        if (t+1 < nk) loadT((t+1)<<5); \
        bf16* base = sm + cur*G_BUF; \
        uint32_t ash = s2u(base), asl = s2u(base+G_ASZ); \
        uint32_t bsh = s2u(base+2*G_ASZ), bsl = s2u(base+2*G_ASZ+G_BSZ); \
        _Pragma("unroll") for (int ks=0; ks<32; ks+=16){ \
            uint32_t ah[4][4], al[4][4]; \
            _Pragma("unroll") for (int mt=0; mt<4; mt++){ \
                uint32_t off = (uint32_t)((wm*64 + mt*16 + ar)*GA_STR + ks + ac8)*2; \
                ldm4(ah[mt], ash + off); \
                ldm4(al[mt], asl + off); \
            } \
            _Pragma("unroll") for (int ntp=0; ntp<2; ntp++){ \
                uint32_t bh[4], bl[4]; \
                uint32_t off = (uint32_t)((ks + ar)*GB_STR + wn*32 + ntp*16 + ac8)*2; \
                ldm4t(bh, bsh + off); \
                ldm4t(bl, bsl + off); \
                _Pragma("unroll") for (int mt=0; mt<4; mt++){ \
                    _Pragma("unroll") for (int sb=0; sb<2; sb++){ \
                        float* c = acc[mt][ntp*2+sb]; \
                        mma16816(c, ah[mt], bh + sb*2); \
                        mma16816(c, ah[mt], bl + sb*2); \
                        mma16816(c, al[mt], bh + sb*2); \
                    } \
                } \
            } \
        } \
        if (t+1 < nk) storeT(cur^1); \
        __syncthreads(); \
        cur ^= 1; \
    }

// ---------------------------------------------------------------------------
// Kernel: plain gemm3 (fp32 C) - for output projection
// ---------------------------------------------------------------------------
__global__ __launch_bounds__(256,1)
void gemm3_kernel(const bf16* __restrict__ Ah, const bf16* __restrict__ Al, int lda,
                  const bf16* __restrict__ Bh, const bf16* __restrict__ Bl, int ldb,
                  float* __restrict__ C, int ldc, int Kd)
{
    GEMM3_MAINLOOP
#pragma unroll
    for (int mt=0; mt<4; mt++){
        int r = m0 + wm*64 + mt*16 + (lane>>2);
#pragma unroll
        for (int nt=0; nt<4; nt++){
            int cc = n0 + wn*32 + nt*8 + 2*(lane&3);
            *(float2*)&C[(size_t)r*ldc + cc]     = make_float2(acc[mt][nt][0], acc[mt][nt][1]);
            *(float2*)&C[(size_t)(r+8)*ldc + cc] = make_float2(acc[mt][nt][2], acc[mt][nt][3]);
        }
    }
}

// ---------------------------------------------------------------------------
// Kernel: QKV gemm3 with fused RMSNorm + RoPE + hi/lo split epilogue.
// N-tile (128) == one head. blockIdx.x: 0-15 q heads, 16-23 k, 24-31 v.
// ---------------------------------------------------------------------------
#define SSTR 132

__global__ __launch_bounds__(256,1)
void gemm3_qkv_kernel(const bf16* __restrict__ Ah, const bf16* __restrict__ Al, int lda,
                      const bf16* __restrict__ Bh, const bf16* __restrict__ Bl, int ldb,
                      bf16* __restrict__ Dh, bf16* __restrict__ Dl,
                      const float2* __restrict__ rope,
                      const float* __restrict__ q_scale,
                      const float* __restrict__ k_scale, int Kd)
{
    GEMM3_MAINLOOP

    // stage acc tile to smem as fp32 [128][SSTR]
    float* stg = (float*)sm;
#pragma unroll
    for (int mt=0; mt<4; mt++){
        int r = wm*64 + mt*16 + (lane>>2);
#pragma unroll
        for (int nt=0; nt<4; nt++){
            int cc = wn*32 + nt*8 + 2*(lane&3);
            *(float2*)&stg[r*SSTR + cc]     = make_float2(acc[mt][nt][0], acc[mt][nt][1]);
            *(float2*)&stg[(r+8)*SSTR + cc] = make_float2(acc[mt][nt][2], acc[mt][nt][3]);
        }
    }
    __syncthreads();

    const int r   = tid >> 1;
    const int hf  = (tid & 1) << 6;      // 0 or 64
    const int grow = m0 + r;
    const int head = blockIdx.x;
    float* stgRow = stg + r*SSTR;
    size_t obase = (size_t)grow*QKV_LD + (size_t)head*128 + hf;

    if (head >= NQH + NKH) {
        // V: plain hi/lo split
#pragma unroll
        for (int p = 0; p < 32; p++){
            uint32_t h, l;
            hl_pack(stgRow[hf + 2*p], stgRow[hf + 2*p + 1], h, l);
            *(uint32_t*)(Dh + obase + 2*p) = h;
            *(uint32_t*)(Dl + obase + 2*p) = l;
        }
    } else {
        float ss = 0.f;
#pragma unroll
        for (int i = 0; i < 16; i++){
            float4 t = *(float4*)&stgRow[hf + i*4];
            ss += t.x*t.x + t.y*t.y + t.z*t.z + t.w*t.w;
        }
        ss += __shfl_xor_sync(0xFFFFFFFFu, ss, 1);
        float rinv = rsqrtf(ss * (1.f/HD) + EPSV);
        const float* sc = (head < NQH) ? q_scale : k_scale;
        const float2* ropeRow = rope + (size_t)grow*64;
#pragma unroll
        for (int p = 0; p < 32; p++){
            float o[2];
#pragma unroll
            for (int u = 0; u < 2; u++){
                int jj = hf + 2*p + u;
                int fj = jj & 63;
                float2 t = ropeRow[fj];
                float xo = sc[jj]      * stgRow[jj]      * rinv;
                float xt = sc[jj ^ 64] * stgRow[jj ^ 64] * rinv;
                o[u] = (hf == 0) ? (xo*t.y - xt*t.x) : (xo*t.y + xt*t.x);
            }
            uint32_t h, l;
            hl_pack(o[0], o[1], h, l);
            *(uint32_t*)(Dh + obase + 2*p) = h;
            *(uint32_t*)(Dl + obase + 2*p) = l;
        }
    }
}

// ---------------------------------------------------------------------------
// Kernel: flash attention with bf16x3 mma (proven R5 version)
// grid (T/64, NQH, B), 128 threads (4 warps); Bq=Bk=64
// ---------------------------------------------------------------------------
#define FSTR 136
#define FLASH_SMEM (6*64*FSTR*2 + 4*64*4)

__global__ __launch_bounds__(128)
void flash3_kernel(const bf16* __restrict__ Gh, const bf16* __restrict__ Gl,
                   const int* __restrict__ pos, const int* __restrict__ seg,
                   bf16* __restrict__ atth, bf16* __restrict__ attl)
{
    extern __shared__ bf16 fsm[];
    bf16* Qh = fsm;           bf16* Ql = Qh + 64*FSTR;
    bf16* Kh = Ql + 64*FSTR;  bf16* Kl = Kh + 64*FSTR;
    bf16* Vh = Kl + 64*FSTR;  bf16* Vl = Vh + 64*FSTR;
    int* posq = (int*)(Vl + 64*FSTR);
    int* segq = posq+64; int* posk = segq+64; int* segk = posk+64;

    const int tid=threadIdx.x, lane=tid&31, warp=tid>>5;
    const int qt=blockIdx.x, n=blockIdx.y, b=blockIdx.z;
    const int kh = n>>1, q0 = qt*64;

#pragma unroll
    for (int i=0;i<8;i++){
        int f = tid + i*128; int r = f>>4; int h8 = (f&15)*8;
        size_t go = (size_t)(b*TT + q0 + r)*QKV_LD + n*HD + h8;
        *(uint4*)(Qh + r*FSTR + h8) = *(const uint4*)(Gh + go);
        *(uint4*)(Ql + r*FSTR + h8) = *(const uint4*)(Gl + go);
    }
    if (tid<64){ posq[tid]=pos[b*TT+q0+tid]; segq[tid]=seg[b*TT+q0+tid]; }
    __syncthreads();

    const int rql = warp*16 + (lane>>2);
    const int pq0=posq[rql], sq0=segq[rql], pq1=posq[rql+8], sq1=segq[rql+8];

    float m0r=NEGI, m1r=NEGI, l0=0.f, l1=0.f;
    float oacc[16][4];
#pragma unroll
    for (int i=0;i<16;i++)
#pragma unroll
        for (int j=0;j<4;j++) oacc[i][j]=0.f;

    uint32_t qh_s = s2u(Qh), ql_s = s2u(Ql), kh_s = s2u(Kh), kl_s = s2u(Kl);
    uint32_t vh_s = s2u(Vh), vl_s = s2u(Vl);

    const int ar = lane&15, ac8 = (lane>>4)*8;
    const int br = ((lane>>4)<<3) + (lane&7), bc8 = lane&8;
    const int cb = 2*(lane&3);

    const int ntk = qt+1;
    for (int kt=0; kt<ntk; kt++){
        const int s0g = kt*64;
#pragma unroll
        for (int i=0;i<8;i++){
            int f = tid + i*128; int r = f>>4; int h8 = (f&15)*8;
            size_t gk = (size_t)(b*TT + s0g + r)*QKV_LD + NQH*HD + kh*HD + h8;
            *(uint4*)(Kh + r*FSTR + h8) = *(const uint4*)(Gh + gk);
            *(uint4*)(Kl + r*FSTR + h8) = *(const uint4*)(Gl + gk);
            size_t gv = gk + NKH*HD;
            *(uint4*)(Vh + r*FSTR + h8) = *(const uint4*)(Gh + gv);
            *(uint4*)(Vl + r*FSTR + h8) = *(const uint4*)(Gl + gv);
        }
        if (tid<64){ posk[tid]=pos[b*TT+s0g+tid]; segk[tid]=seg[b*TT+s0g+tid]; }
        __syncthreads();

        float sacc[8][4];
#pragma unroll
        for (int i=0;i<8;i++)
#pragma unroll
            for (int j=0;j<4;j++) sacc[i][j]=0.f;

#pragma unroll
        for (int ks=0; ks<HD; ks+=16){
            uint32_t ah[4], al[4];
            uint32_t aoff = (uint32_t)((warp*16 + ar)*FSTR + ks + ac8)*2;
            ldm4(ah, qh_s + aoff);
            ldm4(al, ql_s + aoff);
#pragma unroll
            for (int ntp=0; ntp<4; ntp++){
                uint32_t bh[4], bl[4];
                uint32_t boff = (uint32_t)((ntp*16 + br)*FSTR + ks + bc8)*2;
                ldm4(bh, kh_s + boff);
                ldm4(bl, kl_s + boff);
#pragma unroll
                for (int sb=0; sb<2; sb++){
                    float* c = sacc[ntp*2+sb];
                    mma16816(c, ah, bh + sb*2);
                    mma16816(c, ah, bl + sb*2);
                    mma16816(c, al, bh + sb*2);
                }
            }
        }

        float t0=NEGI, t1=NEGI;
#pragma unroll
        for (int nt=0; nt<8; nt++){
            int c0 = nt*8 + cb;
            int pk0=posk[c0], sk0=segk[c0], pk1=posk[c0+1], sk1=segk[c0+1];
            float v00 = (pk0<=pq0 && sk0==sq0) ? sacc[nt][0]*SCALEV : MASKV;
            float v01 = (pk1<=pq0 && sk1==sq0) ? sacc[nt][1]*SCALEV : MASKV;
            float v10 = (pk0<=pq1 && sk0==sq1) ? sacc[nt][2]*SCALEV : MASKV;
            float v11 = (pk1<=pq1 && sk1==sq1) ? sacc[nt][3]*SCALEV : MASKV;
            sacc[nt][0]=v00; sacc[nt][1]=v01; sacc[nt][2]=v10; sacc[nt][3]=v11;
            t0 = fmaxf(t0, fmaxf(v00,v01));
            t1 = fmaxf(t1, fmaxf(v10,v11));
        }
        t0 = fmaxf(t0, __shfl_xor_sync(0xFFFFFFFFu, t0, 1));
        t0 = fmaxf(t0, __shfl_xor_sync(0xFFFFFFFFu, t0, 2));
        t1 = fmaxf(t1, __shfl_xor_sync(0xFFFFFFFFu, t1, 1));
        t1 = fmaxf(t1, __shfl_xor_sync(0xFFFFFFFFu, t1, 2));
        float nm0 = fmaxf(m0r, t0), nm1 = fmaxf(m1r, t1);
        float a0 = __expf(m0r-nm0), a1 = __expf(m1r-nm1);
        float rs0=0.f, rs1=0.f;
#pragma unroll
        for (int nt=0; nt<8; nt++){
            float p00=__expf(sacc[nt][0]-nm0), p01=__expf(sacc[nt][1]-nm0);
            float p10=__expf(sacc[nt][2]-nm1), p11=__expf(sacc[nt][3]-nm1);
            sacc[nt][0]=p00; sacc[nt][1]=p01; sacc[nt][2]=p10; sacc[nt][3]=p11;
            rs0 += p00+p01; rs1 += p10+p11;
        }
        rs0 += __shfl_xor_sync(0xFFFFFFFFu, rs0, 1);
        rs0 += __shfl_xor_sync(0xFFFFFFFFu, rs0, 2);
        rs1 += __shfl_xor_sync(0xFFFFFFFFu, rs1, 1);
        rs1 += __shfl_xor_sync(0xFFFFFFFFu, rs1, 2);
        l0 = l0*a0 + rs0; l1 = l1*a1 + rs1;
        m0r = nm0; m1r = nm1;
#pragma unroll
        for (int nt=0; nt<16; nt++){
            oacc[nt][0]*=a0; oacc[nt][1]*=a0; oacc[nt][2]*=a1; oacc[nt][3]*=a1;
        }

#pragma unroll
        for (int ks=0; ks<4; ks++){
            uint32_t pah[4], pal[4];
            hl_pack(sacc[2*ks][0],   sacc[2*ks][1],   pah[0], pal[0]);
            hl_pack(sacc[2*ks][2],   sacc[2*ks][3],   pah[1], pal[1]);
            hl_pack(sacc[2*ks+1][0], sacc[2*ks+1][1], pah[2], pal[2]);
            hl_pack(sacc[2*ks+1][2], sacc[2*ks+1][3], pah[3], pal[3]);
#pragma unroll
            for (int ntp=0; ntp<8; ntp++){
                uint32_t bh[4], bl[4];
                uint32_t off = (uint32_t)((ks*16 + ar)*FSTR + ntp*16 + ac8)*2;
                ldm4t(bh, vh_s + off);
                ldm4t(bl, vl_s + off);
#pragma unroll
                for (int sb=0; sb<2; sb++){
                    float* c = oacc[ntp*2+sb];
                    mma16816(c, pah, bh + sb*2);
                    mma16816(c, pah, bl + sb*2);
                    mma16816(c, pal, bh + sb*2);
                }
            }
        }
        __syncthreads();
    }

    float il0 = 1.f/l0, il1 = 1.f/l1;
#pragma unroll
    for (int nt=0; nt<16; nt++){
        int hcol = nt*8 + cb;
        size_t o0 = (size_t)(b*TT + q0 + warp*16 + (lane>>2))*ATT_LD + n*HD + hcol;
        uint32_t h, l;
        hl_pack(oacc[nt][0]*il0, oacc[nt][1]*il0, h, l);
        *(uint32_t*)(atth + o0) = h; *(uint32_t*)(attl + o0) = l;
        hl_pack(oacc[nt][2]*il1, oacc[nt][3]*il1, h, l);
        *(uint32_t*)(atth + o0 + 8*ATT_LD) = h; *(uint32_t*)(attl + o0 + 8*ATT_LD) = l;
    }
}

// ---------------------------------------------------------------------------
// Launch
// ---------------------------------------------------------------------------
extern "C" void kernel_launch(void* const* d_in, const int* in_sizes, int n_in,
                              void* d_out, int out_size)
{
    const float* x       = (const float*)d_in[0];
    const int*   seg     = (const int*)d_in[1];
    const float* wq      = (const float*)d_in[2];
    const float* wk      = (const float*)d_in[3];
    const float* wv      = (const float*)d_in[4];
    const float* wo      = (const float*)d_in[5];
    const float* q_scale = (const float*)d_in[6];
    const float* k_scale = (const float*)d_in[7];
    float* out           = (float*)d_out;

    bf16 *xh, *xl, *wh, *wl, *qh, *ql, *ah, *al, *oh, *ol;
    cudaGetSymbolAddress((void**)&xh, g_xh); cudaGetSymbolAddress((void**)&xl, g_xl);
    cudaGetSymbolAddress((void**)&wh, g_wh); cudaGetSymbolAddress((void**)&wl, g_wl);
    cudaGetSymbolAddress((void**)&qh, g_qh); cudaGetSymbolAddress((void**)&ql, g_ql);
    cudaGetSymbolAddress((void**)&ah, g_ah); cudaGetSymbolAddress((void**)&al, g_al);
    cudaGetSymbolAddress((void**)&oh, g_oh); cudaGetSymbolAddress((void**)&ol, g_ol);
    float2* rope; cudaGetSymbolAddress((void**)&rope, g_rope);
    int* pos;     cudaGetSymbolAddress((void**)&pos, g_pos);

    cudaFuncSetAttribute(gemm3_kernel, cudaFuncAttributeMaxDynamicSharedMemorySize, GEMM_SMEM);
    cudaFuncSetAttribute(gemm3_qkv_kernel, cudaFuncAttributeMaxDynamicSharedMemorySize, GEMM_SMEM);
    cudaFuncSetAttribute(flash3_kernel, cudaFuncAttributeMaxDynamicSharedMemorySize, FLASH_SMEM);

    // 1) positions + rope table
    pos_kernel<<<TB, 256>>>(seg, pos);
    rope_kernel<<<(BT*64)/256, 256>>>(pos, rope);

    // 2) splits: x and weights (weights in natural [K][N] layout)
    split_kernel<<<2048, 256>>>(x,  xh, xl, BT, TD, TD, TD, 0);
    split_kernel<<<1024, 256>>>(wq, wh, wl, TD, NQH*HD, NQH*HD, QKV_LD, 0);
    split_kernel<<<512,  256>>>(wk, wh, wl, TD, NKH*HD, NKH*HD, QKV_LD, NQH*HD);
    split_kernel<<<512,  256>>>(wv, wh, wl, TD, NKH*HD, NKH*HD, QKV_LD, NQH*HD + NKH*HD);
    split_kernel<<<1024, 256>>>(wo, oh, ol, ATT_LD, TD, TD, TD, 0);

    // 3) QKV projection + fused RMSNorm/RoPE/split -> qh/ql
    {
        dim3 g(QKV_LD/128, BT/128);
        gemm3_qkv_kernel<<<g, 256, GEMM_SMEM>>>(xh, xl, TD, wh, wl, QKV_LD,
                                                qh, ql, rope, q_scale, k_scale, TD);
    }

    // 4) flash attention (Bq=64, proven)
    {
        dim3 g(TT/64, NQH, TB);
        flash3_kernel<<<g, 128, FLASH_SMEM>>>(qh, ql, pos, seg, ah, al);
    }

    // 5) output projection
    {
        dim3 g(TD/128, BT/128);
        gemm3_kernel<<<g, 256, GEMM_SMEM>>>(ah, al, ATT_LD, oh, ol, TD, out, TD, ATT_LD);
    }
}

// round 13
// speedup vs baseline: 1.0636x; 1.0636x over previous
#include <cuda_runtime.h>
#include <cuda_bf16.h>
#include <math.h>
#include <stdint.h>

#define TB 2
#define TT 2048
#define TD 1024
#define NQH 16
#define NKH 8
#define HD 128
#define BT (TB*TT)          // 4096
#define QKV_LD 4096
#define ATT_LD 2048
#define EPSV 1e-6f
#define SCALEV 0.08838834764831845f
#define LOG2_THETA 19.9315685693241740f
#define MASKV (-3.0e38f)
#define NEGI (-1e30f)

typedef __nv_bfloat16 bf16;
typedef __nv_bfloat162 bf162;

// Scratch (device globals; no runtime allocation)
__device__ float g_qkv[(size_t)BT*QKV_LD];   // 64MB fp32 qkv
__device__ bf16 g_xh[(size_t)BT*TD],     g_xl[(size_t)BT*TD];
__device__ bf16 g_wh[(size_t)TD*QKV_LD], g_wl[(size_t)TD*QKV_LD];
__device__ bf16 g_qh[(size_t)BT*QKV_LD], g_ql[(size_t)BT*QKV_LD];
__device__ bf16 g_ah[(size_t)BT*ATT_LD], g_al[(size_t)BT*ATT_LD];
__device__ bf16 g_oh[(size_t)ATT_LD*TD], g_ol[(size_t)ATT_LD*TD];
__device__ float2 g_rope[(size_t)BT*64];
__device__ int  g_pos[BT];

// ---------------------------------------------------------------------------
// helpers
// ---------------------------------------------------------------------------
__device__ __forceinline__ uint32_t s2u(const void* p){
    return (uint32_t)__cvta_generic_to_shared(p);
}
__device__ __forceinline__ void ldm4(uint32_t* r, uint32_t a){
    asm volatile("ldmatrix.sync.aligned.m8n8.x4.shared.b16 {%0,%1,%2,%3}, [%4];"
        : "=r"(r[0]),"=r"(r[1]),"=r"(r[2]),"=r"(r[3]) : "r"(a));
}
__device__ __forceinline__ void ldm4t(uint32_t* r, uint32_t a){
    asm volatile("ldmatrix.sync.aligned.m8n8.x4.trans.shared.b16 {%0,%1,%2,%3}, [%4];"
        : "=r"(r[0]),"=r"(r[1]),"=r"(r[2]),"=r"(r[3]) : "r"(a));
}
__device__ __forceinline__ void mma16816(float* c, const uint32_t* a, const uint32_t* b){
    asm volatile("mma.sync.aligned.m16n8k16.row.col.f32.bf16.bf16.f32 "
        "{%0,%1,%2,%3}, {%4,%5,%6,%7}, {%8,%9}, {%0,%1,%2,%3};"
        : "+f"(c[0]),"+f"(c[1]),"+f"(c[2]),"+f"(c[3])
        : "r"(a[0]),"r"(a[1]),"r"(a[2]),"r"(a[3]),"r"(b[0]),"r"(b[1]));
}
__device__ __forceinline__ void hl_pack(float x, float y, uint32_t& h, uint32_t& l){
    bf16 hx = __float2bfloat16(x), hy = __float2bfloat16(y);
    bf162 th = __halves2bfloat162(hx, hy);
    h = *reinterpret_cast<uint32_t*>(&th);
    bf162 tl = __floats2bfloat162_rn(x - __bfloat162float(hx), y - __bfloat162float(hy));
    l = *reinterpret_cast<uint32_t*>(&tl);
}
__device__ __forceinline__ void hl_split1(float x, bf16& h, bf16& l){
    h = __float2bfloat16(x);
    l = __float2bfloat16(x - __bfloat162float(h));
}
__device__ __forceinline__ void cpa16(uint32_t s, const void* g){
    asm volatile("cp.async.cg.shared.global [%0], [%1], 16;" :: "r"(s), "l"(g) : "memory");
}
__device__ __forceinline__ void cpa4(uint32_t s, const void* g){
    asm volatile("cp.async.ca.shared.global [%0], [%1], 4;" :: "r"(s), "l"(g) : "memory");
}
__device__ __forceinline__ void cp_commit(){
    asm volatile("cp.async.commit_group;" ::: "memory");
}

// ---------------------------------------------------------------------------
// Kernel: positions from segment ids
// ---------------------------------------------------------------------------
__global__ void pos_kernel(const int* __restrict__ seg, int* __restrict__ pos) {
    const int b = blockIdx.x;
    const int tid = threadIdx.x;
    __shared__ int red[256];
    int mx = -2147483647 - 1;
    for (int t = tid; t < TT; t += 256) mx = max(mx, seg[b*TT + t]);
    red[tid] = mx; __syncthreads();
    for (int s = 128; s > 0; s >>= 1) {
        if (tid < s) red[tid] = max(red[tid], red[tid + s]);
        __syncthreads();
    }
    const int gmax = red[0];
    __syncthreads();
    int idx = TT;
    for (int t = tid; t < TT; t += 256)
        if (seg[b*TT + t] == gmax && t < idx) idx = t;
    red[tid] = idx; __syncthreads();
    for (int s = 128; s > 0; s >>= 1) {
        if (tid < s) red[tid] = min(red[tid], red[tid + s]);
        __syncthreads();
    }
    const int off = red[0];
    for (int t = tid; t < TT; t += 256) {
        int sv = seg[b*TT + t];
        pos[b*TT + t] = (sv != 0) ? (t - off) : (1 << 30);
    }
}

// ---------------------------------------------------------------------------
// Kernel: rope table  rope[bt][j] = (sin, cos)(pos[bt] * theta^-(j/64))
// ---------------------------------------------------------------------------
__global__ void rope_kernel(const int* __restrict__ pos, float2* __restrict__ rope){
    int idx = blockIdx.x*blockDim.x + threadIdx.x;   // BT*64 total
    int bt = idx >> 6, j = idx & 63;
    float inv_freq = exp2f(-(float)j * (LOG2_THETA / 64.f));
    float ang = (float)pos[bt] * inv_freq;
    float s, c;
    sincosf(ang, &s, &c);
    rope[idx] = make_float2(s, c);
}

// ---------------------------------------------------------------------------
// Kernel: fp32 -> bf16 hi/lo split
// ---------------------------------------------------------------------------
__global__ void split_kernel(const float* __restrict__ src, bf16* __restrict__ dh,
                             bf16* __restrict__ dl, int rows, int cols,
                             int sld, int dld, int doff)
{
    const int c4 = cols >> 2;
    const int total = rows * c4;
    for (int i = blockIdx.x*blockDim.x + threadIdx.x; i < total; i += gridDim.x*blockDim.x) {
        int r = i / c4;
        int c = (i - r*c4) * 4;
        float4 v = *(const float4*)&src[(size_t)r*sld + c];
        bf16 h0,h1,h2,h3,l0,l1,l2,l3;
        hl_split1(v.x,h0,l0); hl_split1(v.y,h1,l1);
        hl_split1(v.z,h2,l2); hl_split1(v.w,h3,l3);
        size_t o = (size_t)r*dld + doff + c;
        *(bf162*)&dh[o]   = __halves2bfloat162(h0,h1);
        *(bf162*)&dh[o+2] = __halves2bfloat162(h2,h3);
        *(bf162*)&dl[o]   = __halves2bfloat162(l0,l1);
        *(bf162*)&dl[o+2] = __halves2bfloat162(l2,l3);
    }
}

// ---------------------------------------------------------------------------
// Kernel: RMSNorm + RoPE in-place on fp32 qkv (rope table, no sincosf)
// grid (BT, NQH+NKH), 128 threads
// ---------------------------------------------------------------------------
__global__ void normrope_kernel(float* __restrict__ qkv,
                                const float2* __restrict__ rope,
                                const float* __restrict__ q_scale,
                                const float* __restrict__ k_scale)
{
    const int bt = blockIdx.x;
    const int head = blockIdx.y;
    const int h = threadIdx.x;
    const bool isq = head < NQH;
    const int colbase = isq ? head * HD : (NQH*HD) + (head - NQH) * HD;
    float* base = qkv + (size_t)bt * QKV_LD + colbase;

    float v = base[h];
    float ss = v * v;
#pragma unroll
    for (int d = 16; d > 0; d >>= 1) ss += __shfl_xor_sync(0xFFFFFFFFu, ss, d);
    __shared__ float wsum[4];
    const int lane = h & 31, wid = h >> 5;
    if (lane == 0) wsum[wid] = ss;
    __syncthreads();
    float total = wsum[0] + wsum[1] + wsum[2] + wsum[3];
    float rinv = rsqrtf(total * (1.0f / HD) + EPSV);
    const float* sc = isq ? q_scale : k_scale;
    float nv = sc[h] * v * rinv;

    __shared__ float buf[HD];
    buf[h] = nv;
    __syncthreads();

    if (h < HD/2) {
        float x1 = buf[h];
        float x2 = buf[h + HD/2];
        float2 t = rope[(size_t)bt*64 + h];
        base[h]        = x1 * t.y - x2 * t.x;
        base[h + HD/2] = x2 * t.y + x1 * t.x;
    }
}

// ---------------------------------------------------------------------------
// bf16x3 GEMM (proven R5): 128x128 block, 8 warps, K-step 32, dbl-buffered
// ---------------------------------------------------------------------------
#define GA_STR 40
#define GB_STR 136
#define G_ASZ (128*GA_STR)
#define G_BSZ (32*GB_STR)
#define G_BUF (2*G_ASZ + 2*G_BSZ)
#define GEMM_SMEM (2*G_BUF*2)

__global__ __launch_bounds__(256,1)
void gemm3_kernel(const bf16* __restrict__ Ah, const bf16* __restrict__ Al, int lda,
                  const bf16* __restrict__ Bh, const bf16* __restrict__ Bl, int ldb,
                  float* __restrict__ C, int ldc, int Kd)
{
    extern __shared__ bf16 sm[];
    const int tid = threadIdx.x, lane = tid&31, warp = tid>>5;
    const int wm = warp&1, wn = warp>>1;
    const int m0 = blockIdx.y*128, n0 = blockIdx.x*128;

    float acc[4][4][4];
#pragma unroll
    for (int i=0;i<4;i++)
#pragma unroll
        for (int j=0;j<4;j++)
#pragma unroll
            for (int q=0;q<4;q++) acc[i][j][q]=0.f;

    uint4 ra_h[2], ra_l[2], rb_h[2], rb_l[2];

    auto loadT = [&](int k0){
#pragma unroll
        for (int i=0;i<2;i++){
            int f = tid + i*256;
            int r = f>>2, k8 = (f&3)*8;
            size_t ao = (size_t)(m0+r)*lda + k0 + k8;
            ra_h[i] = *(const uint4*)(Ah+ao);
            ra_l[i] = *(const uint4*)(Al+ao);
            int kr = f>>4, n8 = (f&15)*8;
            size_t bo = (size_t)(k0+kr)*ldb + n0 + n8;
            rb_h[i] = *(const uint4*)(Bh+bo);
            rb_l[i] = *(const uint4*)(Bl+bo);
        }
    };
    auto storeT = [&](int buf){
        bf16* base = sm + buf*G_BUF;
#pragma unroll
        for (int i=0;i<2;i++){
            int f = tid + i*256;
            int r = f>>2, k8 = (f&3)*8;
            *(uint4*)(base + r*GA_STR + k8) = ra_h[i];
            *(uint4*)(base + G_ASZ + r*GA_STR + k8) = ra_l[i];
            int kr = f>>4, n8 = (f&15)*8;
            *(uint4*)(base + 2*G_ASZ + kr*GB_STR + n8) = rb_h[i];
            *(uint4*)(base + 2*G_ASZ + G_BSZ + kr*GB_STR + n8) = rb_l[i];
        }
    };

    const int nk = Kd >> 5;
    loadT(0); storeT(0); __syncthreads();
    int cur = 0;
    const int ar = lane&15, ac8 = (lane>>4)*8;
    for (int t=0; t<nk; t++){
        if (t+1 < nk) loadT((t+1)<<5);
        bf16* base = sm + cur*G_BUF;
        uint32_t ash = s2u(base), asl = s2u(base+G_ASZ);
        uint32_t bsh = s2u(base+2*G_ASZ), bsl = s2u(base+2*G_ASZ+G_BSZ);
#pragma unroll
        for (int ks=0; ks<32; ks+=16){
            uint32_t ah[4][4], al[4][4];
#pragma unroll
            for (int mt=0; mt<4; mt++){
                uint32_t off = (uint32_t)((wm*64 + mt*16 + ar)*GA_STR + ks + ac8)*2;
                ldm4(ah[mt], ash + off);
                ldm4(al[mt], asl + off);
            }
#pragma unroll
            for (int ntp=0; ntp<2; ntp++){
                uint32_t bh[4], bl[4];
                uint32_t off = (uint32_t)((ks + ar)*GB_STR + wn*32 + ntp*16 + ac8)*2;
                ldm4t(bh, bsh + off);
                ldm4t(bl, bsl + off);
#pragma unroll
                for (int mt=0; mt<4; mt++){
#pragma unroll
                    for (int sb=0; sb<2; sb++){
                        float* c = acc[mt][ntp*2+sb];
                        mma16816(c, ah[mt], bh + sb*2);
                        mma16816(c, ah[mt], bl + sb*2);
                        mma16816(c, al[mt], bh + sb*2);
                    }
                }
            }
        }
        if (t+1 < nk) storeT(cur^1);
        __syncthreads();
        cur ^= 1;
    }
#pragma unroll
    for (int mt=0; mt<4; mt++){
        int r = m0 + wm*64 + mt*16 + (lane>>2);
#pragma unroll
        for (int nt=0; nt<4; nt++){
            int cc = n0 + wn*32 + nt*8 + 2*(lane&3);
            *(float2*)&C[(size_t)r*ldc + cc]     = make_float2(acc[mt][nt][0], acc[mt][nt][1]);
            *(float2*)&C[(size_t)(r+8)*ldc + cc] = make_float2(acc[mt][nt][2], acc[mt][nt][3]);
        }
    }
}

// ---------------------------------------------------------------------------
// Kernel: flash attention, Bq=64, Bk=32, 128 threads, cp.async double-buffered
// K/V, Q fragments register-resident. grid (T/64, NQH, B)
// ---------------------------------------------------------------------------
#define FKT 32
#define FSTR 136
#define KVE (FKT*FSTR)
#define FLASH_SMEM ((2*64*FSTR + 8*KVE)*2 + 256*4)

__global__ __launch_bounds__(128)
void flash3_kernel(const bf16* __restrict__ Gh, const bf16* __restrict__ Gl,
                   const int* __restrict__ pos, const int* __restrict__ seg,
                   bf16* __restrict__ atth, bf16* __restrict__ attl)
{
    extern __shared__ bf16 fsm[];
    bf16* Qh_s = fsm;                  // 64 x FSTR
    bf16* Ql_s = Qh_s + 64*FSTR;
    bf16* KVb  = Ql_s + 64*FSTR;       // [2][Kh,Kl,Vh,Vl] x KVE
    int* posq  = (int*)(KVb + 8*KVE);  // 64
    int* segq  = posq + 64;
    int* poskA = segq + 64;            // [2][32]
    int* segkA = poskA + 64;

    const int tid=threadIdx.x, lane=tid&31, warp=tid>>5;
    const int qt=blockIdx.x, n=blockIdx.y, b=blockIdx.z;
    const int kh = n>>1, q0 = qt*64;

    auto issue_kv = [&](int kt, int db){
        bf16* base = KVb + db*4*KVE;
        const int s0g = kt*FKT;
        // 32 rows x 16 col-chunks = 512 transfers per matrix; 4 per thread
#pragma unroll
        for (int i=0;i<4;i++){
            int f = tid + i*128;                  // 0..511
            int r = f>>4, c8 = (f&15)*8;          // row 0..31, chunk 0..15
            size_t gk = (size_t)(b*TT + s0g + r)*QKV_LD + NQH*HD + kh*HD + c8;
            uint32_t so = (uint32_t)(r*FSTR + c8)*2;
            cpa16(s2u(base) + so,         Gh + gk);
            cpa16(s2u(base + KVE) + so,   Gl + gk);
            cpa16(s2u(base + 2*KVE) + so, Gh + gk + NKH*HD);
            cpa16(s2u(base + 3*KVE) + so, Gl + gk + NKH*HD);
        }
        if (tid < 32)      cpa4(s2u(poskA + db*32 + tid),      pos + b*TT + s0g + tid);
        else if (tid < 64) cpa4(s2u(segkA + db*32 + (tid-32)), seg + b*TT + s0g + (tid-32));
        cp_commit();
    };

    // start K/V pipeline immediately, overlap with Q load
    issue_kv(0, 0);

    // Q tile -> smem (normal loads)
#pragma unroll
    for (int i=0;i<8;i++){
        int f = tid + i*128; int r = f>>4; int h8 = (f&15)*8;
        size_t go = (size_t)(b*TT + q0 + r)*QKV_LD + n*HD + h8;
        *(uint4*)(Qh_s + r*FSTR + h8) = *(const uint4*)(Gh + go);
        *(uint4*)(Ql_s + r*FSTR + h8) = *(const uint4*)(Gl + go);
    }
    if (tid<64){ posq[tid]=pos[b*TT+q0+tid]; segq[tid]=seg[b*TT+q0+tid]; }
    __syncthreads();

    const int ar = lane&15, ac8 = (lane>>4)*8;
    const int br = ((lane>>4)<<3) + (lane&7), bc8 = lane&8;
    const int cb = 2*(lane&3);

    // Q fragments -> registers (used for every tile; Q smem not touched again)
    uint32_t qfh[8][4], qfl[8][4];
    {
        const uint32_t qh_s = s2u(Qh_s), ql_s = s2u(Ql_s);
#pragma unroll
        for (int ks=0; ks<8; ks++){
            uint32_t aoff = (uint32_t)((warp*16 + ar)*FSTR + ks*16 + ac8)*2;
            ldm4(qfh[ks], qh_s + aoff);
            ldm4(qfl[ks], ql_s + aoff);
        }
    }

    const int rql = warp*16 + (lane>>2);
    const int pq0=posq[rql], sq0=segq[rql], pq1=posq[rql+8], sq1=segq[rql+8];

    float m0r=NEGI, m1r=NEGI, l0=0.f, l1=0.f;
    float oacc[16][4];
#pragma unroll
    for (int i=0;i<16;i++)
#pragma unroll
        for (int j=0;j<4;j++) oacc[i][j]=0.f;

    const int ntk = 2*qt + 2;
    int db = 0;
    for (int kt=0; kt<ntk; kt++){
        if (kt+1 < ntk){
            issue_kv(kt+1, db^1);
            asm volatile("cp.async.wait_group 1;" ::: "memory");
        } else {
            asm volatile("cp.async.wait_group 0;" ::: "memory");
        }
        __syncthreads();

        bf16* base = KVb + db*4*KVE;
        const uint32_t kh_s = s2u(base),          kl_s = s2u(base + KVE);
        const uint32_t vh_s = s2u(base + 2*KVE),  vl_s = s2u(base + 3*KVE);
        const int* posk = poskA + db*32;
        const int* segk = segkA + db*32;

        float sacc[4][4];
#pragma unroll
        for (int i=0;i<4;i++)
#pragma unroll
            for (int j=0;j<4;j++) sacc[i][j]=0.f;

        // ---- S = Q K^T (16 q-rows x 32 k-cols per warp) ----
#pragma unroll
        for (int ks=0; ks<8; ks++){
#pragma unroll
            for (int ntp=0; ntp<2; ntp++){
                uint32_t bh[4], bl[4];
                uint32_t boff = (uint32_t)((ntp*16 + br)*FSTR + ks*16 + bc8)*2;
                ldm4(bh, kh_s + boff);
                ldm4(bl, kl_s + boff);
#pragma unroll
                for (int sb=0; sb<2; sb++){
                    float* c = sacc[ntp*2+sb];
                    mma16816(c, qfh[ks], bh + sb*2);
                    mma16816(c, qfh[ks], bl + sb*2);
                    mma16816(c, qfl[ks], bh + sb*2);
                }
            }
        }

        // ---- scale + mask + online softmax ----
        float t0=NEGI, t1=NEGI;
#pragma unroll
        for (int nt=0; nt<4; nt++){
            int c0 = nt*8 + cb;
            int pk0=posk[c0], sk0=segk[c0], pk1=posk[c0+1], sk1=segk[c0+1];
            float v00 = (pk0<=pq0 && sk0==sq0) ? sacc[nt][0]*SCALEV : MASKV;
            float v01 = (pk1<=pq0 && sk1==sq0) ? sacc[nt][1]*SCALEV : MASKV;
            float v10 = (pk0<=pq1 && sk0==sq1) ? sacc[nt][2]*SCALEV : MASKV;
            float v11 = (pk1<=pq1 && sk1==sq1) ? sacc[nt][3]*SCALEV : MASKV;
            sacc[nt][0]=v00; sacc[nt][1]=v01; sacc[nt][2]=v10; sacc[nt][3]=v11;
            t0 = fmaxf(t0, fmaxf(v00,v01));
            t1 = fmaxf(t1, fmaxf(v10,v11));
        }
        t0 = fmaxf(t0, __shfl_xor_sync(0xFFFFFFFFu, t0, 1));
        t0 = fmaxf(t0, __shfl_xor_sync(0xFFFFFFFFu, t0, 2));
        t1 = fmaxf(t1, __shfl_xor_sync(0xFFFFFFFFu, t1, 1));
        t1 = fmaxf(t1, __shfl_xor_sync(0xFFFFFFFFu, t1, 2));
        float nm0 = fmaxf(m0r, t0), nm1 = fmaxf(m1r, t1);
        float a0 = __expf(m0r-nm0), a1 = __expf(m1r-nm1);
        float rs0=0.f, rs1=0.f;
#pragma unroll
        for (int nt=0; nt<4; nt++){
            float p00=__expf(sacc[nt][0]-nm0), p01=__expf(sacc[nt][1]-nm0);
            float p10=__expf(sacc[nt][2]-nm1), p11=__expf(sacc[nt][3]-nm1);
            sacc[nt][0]=p00; sacc[nt][1]=p01; sacc[nt][2]=p10; sacc[nt][3]=p11;
            rs0 += p00+p01; rs1 += p10+p11;
        }
        rs0 += __shfl_xor_sync(0xFFFFFFFFu, rs0, 1);
        rs0 += __shfl_xor_sync(0xFFFFFFFFu, rs0, 2);
        rs1 += __shfl_xor_sync(0xFFFFFFFFu, rs1, 1);
        rs1 += __shfl_xor_sync(0xFFFFFFFFu, rs1, 2);
        l0 = l0*a0 + rs0; l1 = l1*a1 + rs1;
        m0r = nm0; m1r = nm1;
#pragma unroll
        for (int nt=0; nt<16; nt++){
            oacc[nt][0]*=a0; oacc[nt][1]*=a0; oacc[nt][2]*=a1; oacc[nt][3]*=a1;
        }

        // ---- O += P V (P 16x32, V 32x128) ----
#pragma unroll
        for (int ks=0; ks<2; ks++){
            uint32_t pah[4], pal[4];
            hl_pack(sacc[2*ks][0],   sacc[2*ks][1],   pah[0], pal[0]);
            hl_pack(sacc[2*ks][2],   sacc[2*ks][3],   pah[1], pal[1]);
            hl_pack(sacc[2*ks+1][0], sacc[2*ks+1][1], pah[2], pal[2]);
            hl_pack(sacc[2*ks+1][2], sacc[2*ks+1][3], pah[3], pal[3]);
#pragma unroll
            for (int ntp=0; ntp<8; ntp++){
                uint32_t bh[4], bl[4];
                uint32_t off = (uint32_t)((ks*16 + ar)*FSTR + ntp*16 + ac8)*2;
                ldm4t(bh, vh_s + off);
                ldm4t(bl, vl_s + off);
#pragma unroll
                for (int sb=0; sb<2; sb++){
                    float* c = oacc[ntp*2+sb];
                    mma16816(c, pah, bh + sb*2);
                    mma16816(c, pah, bl + sb*2);
                    mma16816(c, pal, bh + sb*2);
                }
            }
        }
        __syncthreads();
        db ^= 1;
    }

    // ---- epilogue ----
    float il0 = 1.f/l0, il1 = 1.f/l1;
#pragma unroll
    for (int nt=0; nt<16; nt++){
        int hcol = nt*8 + cb;
        size_t o0 = (size_t)(b*TT + q0 + warp*16 + (lane>>2))*ATT_LD + n*HD + hcol;
        uint32_t h, l;
        hl_pack(oacc[nt][0]*il0, oacc[nt][1]*il0, h, l);
        *(uint32_t*)(atth + o0) = h; *(uint32_t*)(attl + o0) = l;
        hl_pack(oacc[nt][2]*il1, oacc[nt][3]*il1, h, l);
        *(uint32_t*)(atth + o0 + 8*ATT_LD) = h; *(uint32_t*)(attl + o0 + 8*ATT_LD) = l;
    }
}

// ---------------------------------------------------------------------------
// Launch
// ---------------------------------------------------------------------------
extern "C" void kernel_launch(void* const* d_in, const int* in_sizes, int n_in,
                              void* d_out, int out_size)
{
    const float* x       = (const float*)d_in[0];
    const int*   seg     = (const int*)d_in[1];
    const float* wq      = (const float*)d_in[2];
    const float* wk      = (const float*)d_in[3];
    const float* wv      = (const float*)d_in[4];
    const float* wo      = (const float*)d_in[5];
    const float* q_scale = (const float*)d_in[6];
    const float* k_scale = (const float*)d_in[7];
    float* out           = (float*)d_out;

    float* qkv; cudaGetSymbolAddress((void**)&qkv, g_qkv);
    bf16 *xh, *xl, *wh, *wl, *qh, *ql, *ah, *al, *oh, *ol;
    cudaGetSymbolAddress((void**)&xh, g_xh); cudaGetSymbolAddress((void**)&xl, g_xl);
    cudaGetSymbolAddress((void**)&wh, g_wh); cudaGetSymbolAddress((void**)&wl, g_wl);
    cudaGetSymbolAddress((void**)&qh, g_qh); cudaGetSymbolAddress((void**)&ql, g_ql);
    cudaGetSymbolAddress((void**)&ah, g_ah); cudaGetSymbolAddress((void**)&al, g_al);
    cudaGetSymbolAddress((void**)&oh, g_oh); cudaGetSymbolAddress((void**)&ol, g_ol);
    float2* rope; cudaGetSymbolAddress((void**)&rope, g_rope);
    int* pos;     cudaGetSymbolAddress((void**)&pos, g_pos);

    cudaFuncSetAttribute(gemm3_kernel, cudaFuncAttributeMaxDynamicSharedMemorySize, GEMM_SMEM);
    cudaFuncSetAttribute(flash3_kernel, cudaFuncAttributeMaxDynamicSharedMemorySize, FLASH_SMEM);

    // 1) positions + rope table
    pos_kernel<<<TB, 256>>>(seg, pos);
    rope_kernel<<<(BT*64)/256, 256>>>(pos, rope);

    // 2) split inputs / weights to bf16 hi/lo
    split_kernel<<<2048, 256>>>(x,  xh, xl, BT, TD, TD, TD, 0);
    split_kernel<<<1024, 256>>>(wq, wh, wl, TD, NQH*HD, NQH*HD, QKV_LD, 0);
    split_kernel<<<512,  256>>>(wk, wh, wl, TD, NKH*HD, NKH*HD, QKV_LD, NQH*HD);
    split_kernel<<<512,  256>>>(wv, wh, wl, TD, NKH*HD, NKH*HD, QKV_LD, NQH*HD + NKH*HD);
    split_kernel<<<1024, 256>>>(wo, oh, ol, ATT_LD, TD, TD, TD, 0);

    // 3) QKV projection (bf16x3 tensor-core GEMM) -> fp32 qkv
    {
        dim3 g(QKV_LD/128, BT/128);
        gemm3_kernel<<<g, 256, GEMM_SMEM>>>(xh, xl, TD, wh, wl, QKV_LD, qkv, QKV_LD, TD);
    }

    // 4) RMSNorm + RoPE (fp32, in place, rope table)
    {
        dim3 g(BT, NQH + NKH);
        normrope_kernel<<<g, HD>>>(qkv, rope, q_scale, k_scale);
    }

    // 5) split qkv to bf16 hi/lo
    split_kernel<<<4096, 256>>>(qkv, qh, ql, BT, QKV_LD, QKV_LD, QKV_LD, 0);

    // 6) flash attention (Bk=32 cp.async pipeline, Q in registers)
    {
        dim3 g(TT/64, NQH, TB);
        flash3_kernel<<<g, 128, FLASH_SMEM>>>(qh, ql, pos, seg, ah, al);
    }

    // 7) output projection
    {
        dim3 g(TD/128, BT/128);
        gemm3_kernel<<<g, 256, GEMM_SMEM>>>(ah, al, ATT_LD, oh, ol, TD, out, TD, ATT_LD);
    }
}

// round 14
// speedup vs baseline: 1.0789x; 1.0144x over previous
#include <cuda_runtime.h>
#include <cuda_bf16.h>
#include <math.h>
#include <stdint.h>

#define TB 2
#define TT 2048
#define TD 1024
#define NQH 16
#define NKH 8
#define HD 128
#define BT (TB*TT)          // 4096
#define QKV_LD 4096
#define ATT_LD 2048
#define EPSV 1e-6f
#define SCALEV 0.08838834764831845f
#define LOG2_THETA 19.9315685693241740f
#define MASKV (-3.0e38f)
#define NEGI (-1e30f)

typedef __nv_bfloat16 bf16;
typedef __nv_bfloat162 bf162;

// Scratch (device globals; no runtime allocation)
__device__ float g_qkv[(size_t)BT*QKV_LD];   // 64MB fp32 qkv
__device__ bf16 g_xh[(size_t)BT*TD],     g_xl[(size_t)BT*TD];
__device__ bf16 g_wh[(size_t)TD*QKV_LD], g_wl[(size_t)TD*QKV_LD];
__device__ bf16 g_qh[(size_t)BT*QKV_LD], g_ql[(size_t)BT*QKV_LD];
__device__ bf16 g_ah[(size_t)BT*ATT_LD], g_al[(size_t)BT*ATT_LD];
__device__ bf16 g_oh[(size_t)ATT_LD*TD], g_ol[(size_t)ATT_LD*TD];
__device__ float2 g_rope[(size_t)BT*64];
__device__ int  g_pos[BT];

// ---------------------------------------------------------------------------
// helpers
// ---------------------------------------------------------------------------
__device__ __forceinline__ uint32_t s2u(const void* p){
    return (uint32_t)__cvta_generic_to_shared(p);
}
__device__ __forceinline__ void ldm4(uint32_t* r, uint32_t a){
    asm volatile("ldmatrix.sync.aligned.m8n8.x4.shared.b16 {%0,%1,%2,%3}, [%4];"
        : "=r"(r[0]),"=r"(r[1]),"=r"(r[2]),"=r"(r[3]) : "r"(a));
}
__device__ __forceinline__ void ldm4t(uint32_t* r, uint32_t a){
    asm volatile("ldmatrix.sync.aligned.m8n8.x4.trans.shared.b16 {%0,%1,%2,%3}, [%4];"
        : "=r"(r[0]),"=r"(r[1]),"=r"(r[2]),"=r"(r[3]) : "r"(a));
}
__device__ __forceinline__ void mma16816(float* c, const uint32_t* a, const uint32_t* b){
    asm volatile("mma.sync.aligned.m16n8k16.row.col.f32.bf16.bf16.f32 "
        "{%0,%1,%2,%3}, {%4,%5,%6,%7}, {%8,%9}, {%0,%1,%2,%3};"
        : "+f"(c[0]),"+f"(c[1]),"+f"(c[2]),"+f"(c[3])
        : "r"(a[0]),"r"(a[1]),"r"(a[2]),"r"(a[3]),"r"(b[0]),"r"(b[1]));
}
__device__ __forceinline__ void hl_pack(float x, float y, uint32_t& h, uint32_t& l){
    bf16 hx = __float2bfloat16(x), hy = __float2bfloat16(y);
    bf162 th = __halves2bfloat162(hx, hy);
    h = *reinterpret_cast<uint32_t*>(&th);
    bf162 tl = __floats2bfloat162_rn(x - __bfloat162float(hx), y - __bfloat162float(hy));
    l = *reinterpret_cast<uint32_t*>(&tl);
}
__device__ __forceinline__ void hl_split1(float x, bf16& h, bf16& l){
    h = __float2bfloat16(x);
    l = __float2bfloat16(x - __bfloat162float(h));
}
__device__ __forceinline__ void cpa16(uint32_t s, const void* g){
    asm volatile("cp.async.cg.shared.global [%0], [%1], 16;" :: "r"(s), "l"(g) : "memory");
}
__device__ __forceinline__ void cpa4(uint32_t s, const void* g){
    asm volatile("cp.async.ca.shared.global [%0], [%1], 4;" :: "r"(s), "l"(g) : "memory");
}
__device__ __forceinline__ void cp_commit(){
    asm volatile("cp.async.commit_group;" ::: "memory");
}

// ---------------------------------------------------------------------------
// Kernel: positions from segment ids
// ---------------------------------------------------------------------------
__global__ void pos_kernel(const int* __restrict__ seg, int* __restrict__ pos) {
    const int b = blockIdx.x;
    const int tid = threadIdx.x;
    __shared__ int red[256];
    int mx = -2147483647 - 1;
    for (int t = tid; t < TT; t += 256) mx = max(mx, seg[b*TT + t]);
    red[tid] = mx; __syncthreads();
    for (int s = 128; s > 0; s >>= 1) {
        if (tid < s) red[tid] = max(red[tid], red[tid + s]);
        __syncthreads();
    }
    const int gmax = red[0];
    __syncthreads();
    int idx = TT;
    for (int t = tid; t < TT; t += 256)
        if (seg[b*TT + t] == gmax && t < idx) idx = t;
    red[tid] = idx; __syncthreads();
    for (int s = 128; s > 0; s >>= 1) {
        if (tid < s) red[tid] = min(red[tid], red[tid + s]);
        __syncthreads();
    }
    const int off = red[0];
    for (int t = tid; t < TT; t += 256) {
        int sv = seg[b*TT + t];
        pos[b*TT + t] = (sv != 0) ? (t - off) : (1 << 30);
    }
}

// ---------------------------------------------------------------------------
// Kernel: rope table  rope[bt][j] = (sin, cos)(pos[bt] * theta^-(j/64))
// ---------------------------------------------------------------------------
__global__ void rope_kernel(const int* __restrict__ pos, float2* __restrict__ rope){
    int idx = blockIdx.x*blockDim.x + threadIdx.x;   // BT*64 total
    int bt = idx >> 6, j = idx & 63;
    float inv_freq = exp2f(-(float)j * (LOG2_THETA / 64.f));
    float ang = (float)pos[bt] * inv_freq;
    float s, c;
    sincosf(ang, &s, &c);
    rope[idx] = make_float2(s, c);
}

// ---------------------------------------------------------------------------
// Kernel: combined hi/lo split for x, wq, wk, wv, wo (one launch)
// flat grid-stride over float4 groups across 5 segments
// ---------------------------------------------------------------------------
#define XG   1048576                 // 4096*1024/4
#define WQG  524288                  // 1024*2048/4
#define WKG  262144                  // 1024*1024/4
#define WVG  262144
#define WOG  524288                  // 2048*1024/4
#define TOTG (XG + WQG + WKG + WVG + WOG)

__device__ __forceinline__ void seg_split(const float* __restrict__ src,
                                          bf16* __restrict__ dh, bf16* __restrict__ dl,
                                          int g, int gpr, int sld, int dld, int doff)
{
    int r = g / gpr;
    int c = (g - r*gpr) * 4;
    float4 v = *(const float4*)&src[(size_t)r*sld + c];
    bf16 h0,h1,h2,h3,l0,l1,l2,l3;
    hl_split1(v.x,h0,l0); hl_split1(v.y,h1,l1);
    hl_split1(v.z,h2,l2); hl_split1(v.w,h3,l3);
    size_t o = (size_t)r*dld + doff + c;
    *(bf162*)&dh[o]   = __halves2bfloat162(h0,h1);
    *(bf162*)&dh[o+2] = __halves2bfloat162(h2,h3);
    *(bf162*)&dl[o]   = __halves2bfloat162(l0,l1);
    *(bf162*)&dl[o+2] = __halves2bfloat162(l2,l3);
}

__global__ void split_all_kernel(const float* __restrict__ x,
                                 const float* __restrict__ wq,
                                 const float* __restrict__ wk,
                                 const float* __restrict__ wv,
                                 const float* __restrict__ wo,
                                 bf16* __restrict__ xh, bf16* __restrict__ xl,
                                 bf16* __restrict__ wh, bf16* __restrict__ wl,
                                 bf16* __restrict__ oh, bf16* __restrict__ ol)
{
    for (int i = blockIdx.x*blockDim.x + threadIdx.x; i < TOTG; i += gridDim.x*blockDim.x) {
        if (i < XG) {
            seg_split(x, xh, xl, i, TD/4, TD, TD, 0);
        } else if (i < XG + WQG) {
            seg_split(wq, wh, wl, i - XG, (NQH*HD)/4, NQH*HD, QKV_LD, 0);
        } else if (i < XG + WQG + WKG) {
            seg_split(wk, wh, wl, i - XG - WQG, (NKH*HD)/4, NKH*HD, QKV_LD, NQH*HD);
        } else if (i < XG + WQG + WKG + WVG) {
            seg_split(wv, wh, wl, i - XG - WQG - WKG, (NKH*HD)/4, NKH*HD, QKV_LD, NQH*HD + NKH*HD);
        } else {
            seg_split(wo, oh, ol, i - XG - WQG - WKG - WVG, TD/4, TD, TD, 0);
        }
    }
}

// ---------------------------------------------------------------------------
// Kernel: RMSNorm + RoPE + hi/lo split, fp32 qkv -> qh/ql (all 32 head slots)
// grid (BT, 32), 128 threads. Slots 0-15 q, 16-23 k, 24-31 v (split only).
// ---------------------------------------------------------------------------
__global__ void normrope_split_kernel(const float* __restrict__ qkv,
                                      const float2* __restrict__ rope,
                                      const float* __restrict__ q_scale,
                                      const float* __restrict__ k_scale,
                                      bf16* __restrict__ dh, bf16* __restrict__ dl)
{
    __shared__ float wsum[4];
    __shared__ float buf[HD];

    const int bt = blockIdx.x;
    const int s  = blockIdx.y;
    const int h  = threadIdx.x;
    const float* base = qkv + (size_t)bt*QKV_LD + (size_t)s*HD;

    float v = base[h];
    float out;
    if (s < NQH + NKH) {
        float ss = v * v;
#pragma unroll
        for (int d = 16; d > 0; d >>= 1) ss += __shfl_xor_sync(0xFFFFFFFFu, ss, d);
        const int lane = h & 31, wid = h >> 5;
        if (lane == 0) wsum[wid] = ss;
        __syncthreads();
        float total = wsum[0] + wsum[1] + wsum[2] + wsum[3];
        float rinv = rsqrtf(total * (1.0f / HD) + EPSV);
        const float* sc = (s < NQH) ? q_scale : k_scale;
        float nv = sc[h] * v * rinv;
        buf[h] = nv;
        __syncthreads();
        const int f = h & 63;
        float2 t = rope[(size_t)bt*64 + f];
        float x1 = buf[f], x2 = buf[f + 64];
        out = (h < 64) ? (x1*t.y - x2*t.x) : (x2*t.y + x1*t.x);
    } else {
        out = v;
    }
    bf16 hh, ll;
    hl_split1(out, hh, ll);
    size_t o = (size_t)bt*QKV_LD + (size_t)s*HD + h;
    dh[o] = hh;
    dl[o] = ll;
}

// ---------------------------------------------------------------------------
// bf16x3 GEMM (proven R5): 128x128 block, 8 warps, K-step 32, dbl-buffered
// ---------------------------------------------------------------------------
#define GA_STR 40
#define GB_STR 136
#define G_ASZ (128*GA_STR)
#define G_BSZ (32*GB_STR)
#define G_BUF (2*G_ASZ + 2*G_BSZ)
#define GEMM_SMEM (2*G_BUF*2)

__global__ __launch_bounds__(256,1)
void gemm3_kernel(const bf16* __restrict__ Ah, const bf16* __restrict__ Al, int lda,
                  const bf16* __restrict__ Bh, const bf16* __restrict__ Bl, int ldb,
                  float* __restrict__ C, int ldc, int Kd)
{
    extern __shared__ bf16 sm[];
    const int tid = threadIdx.x, lane = tid&31, warp = tid>>5;
    const int wm = warp&1, wn = warp>>1;
    const int m0 = blockIdx.y*128, n0 = blockIdx.x*128;

    float acc[4][4][4];
#pragma unroll
    for (int i=0;i<4;i++)
#pragma unroll
        for (int j=0;j<4;j++)
#pragma unroll
            for (int q=0;q<4;q++) acc[i][j][q]=0.f;

    uint4 ra_h[2], ra_l[2], rb_h[2], rb_l[2];

    auto loadT = [&](int k0){
#pragma unroll
        for (int i=0;i<2;i++){
            int f = tid + i*256;
            int r = f>>2, k8 = (f&3)*8;
            size_t ao = (size_t)(m0+r)*lda + k0 + k8;
            ra_h[i] = *(const uint4*)(Ah+ao);
            ra_l[i] = *(const uint4*)(Al+ao);
            int kr = f>>4, n8 = (f&15)*8;
            size_t bo = (size_t)(k0+kr)*ldb + n0 + n8;
            rb_h[i] = *(const uint4*)(Bh+bo);
            rb_l[i] = *(const uint4*)(Bl+bo);
        }
    };
    auto storeT = [&](int buf){
        bf16* base = sm + buf*G_BUF;
#pragma unroll
        for (int i=0;i<2;i++){
            int f = tid + i*256;
            int r = f>>2, k8 = (f&3)*8;
            *(uint4*)(base + r*GA_STR + k8) = ra_h[i];
            *(uint4*)(base + G_ASZ + r*GA_STR + k8) = ra_l[i];
            int kr = f>>4, n8 = (f&15)*8;
            *(uint4*)(base + 2*G_ASZ + kr*GB_STR + n8) = rb_h[i];
            *(uint4*)(base + 2*G_ASZ + G_BSZ + kr*GB_STR + n8) = rb_l[i];
        }
    };

    const int nk = Kd >> 5;
    loadT(0); storeT(0); __syncthreads();
    int cur = 0;
    const int ar = lane&15, ac8 = (lane>>4)*8;
    for (int t=0; t<nk; t++){
        if (t+1 < nk) loadT((t+1)<<5);
        bf16* base = sm + cur*G_BUF;
        uint32_t ash = s2u(base), asl = s2u(base+G_ASZ);
        uint32_t bsh = s2u(base+2*G_ASZ), bsl = s2u(base+2*G_ASZ+G_BSZ);
#pragma unroll
        for (int ks=0; ks<32; ks+=16){
            uint32_t ah[4][4], al[4][4];
#pragma unroll
            for (int mt=0; mt<4; mt++){
                uint32_t off = (uint32_t)((wm*64 + mt*16 + ar)*GA_STR + ks + ac8)*2;
                ldm4(ah[mt], ash + off);
                ldm4(al[mt], asl + off);
            }
#pragma unroll
            for (int ntp=0; ntp<2; ntp++){
                uint32_t bh[4], bl[4];
                uint32_t off = (uint32_t)((ks + ar)*GB_STR + wn*32 + ntp*16 + ac8)*2;
                ldm4t(bh, bsh + off);
                ldm4t(bl, bsl + off);
#pragma unroll
                for (int mt=0; mt<4; mt++){
#pragma unroll
                    for (int sb=0; sb<2; sb++){
                        float* c = acc[mt][ntp*2+sb];
                        mma16816(c, ah[mt], bh + sb*2);
                        mma16816(c, ah[mt], bl + sb*2);
                        mma16816(c, al[mt], bh + sb*2);
                    }
                }
            }
        }
        if (t+1 < nk) storeT(cur^1);
        __syncthreads();
        cur ^= 1;
    }
#pragma unroll
    for (int mt=0; mt<4; mt++){
        int r = m0 + wm*64 + mt*16 + (lane>>2);
#pragma unroll
        for (int nt=0; nt<4; nt++){
            int cc = n0 + wn*32 + nt*8 + 2*(lane&3);
            *(float2*)&C[(size_t)r*ldc + cc]     = make_float2(acc[mt][nt][0], acc[mt][nt][1]);
            *(float2*)&C[(size_t)(r+8)*ldc + cc] = make_float2(acc[mt][nt][2], acc[mt][nt][3]);
        }
    }
}

// ---------------------------------------------------------------------------
// Kernel: flash attention, Bq=64, Bk=32, 128 threads, cp.async double-buffered
// K/V, Q fragments register-resident. grid (T/64, NQH, B)  [proven R13]
// ---------------------------------------------------------------------------
#define FKT 32
#define FSTR 136
#define KVE (FKT*FSTR)
#define FLASH_SMEM ((2*64*FSTR + 8*KVE)*2 + 256*4)

__global__ __launch_bounds__(128)
void flash3_kernel(const bf16* __restrict__ Gh, const bf16* __restrict__ Gl,
                   const int* __restrict__ pos, const int* __restrict__ seg,
                   bf16* __restrict__ atth, bf16* __restrict__ attl)
{
    extern __shared__ bf16 fsm[];
    bf16* Qh_s = fsm;                  // 64 x FSTR
    bf16* Ql_s = Qh_s + 64*FSTR;
    bf16* KVb  = Ql_s + 64*FSTR;       // [2][Kh,Kl,Vh,Vl] x KVE
    int* posq  = (int*)(KVb + 8*KVE);  // 64
    int* segq  = posq + 64;
    int* poskA = segq + 64;            // [2][32]
    int* segkA = poskA + 64;

    const int tid=threadIdx.x, lane=tid&31, warp=tid>>5;
    const int qt=blockIdx.x, n=blockIdx.y, b=blockIdx.z;
    const int kh = n>>1, q0 = qt*64;

    auto issue_kv = [&](int kt, int db){
        bf16* base = KVb + db*4*KVE;
        const int s0g = kt*FKT;
        // 32 rows x 16 col-chunks = 512 transfers per matrix; 4 per thread
#pragma unroll
        for (int i=0;i<4;i++){
            int f = tid + i*128;                  // 0..511
            int r = f>>4, c8 = (f&15)*8;          // row 0..31, chunk 0..15
            size_t gk = (size_t)(b*TT + s0g + r)*QKV_LD + NQH*HD + kh*HD + c8;
            uint32_t so = (uint32_t)(r*FSTR + c8)*2;
            cpa16(s2u(base) + so,         Gh + gk);
            cpa16(s2u(base + KVE) + so,   Gl + gk);
            cpa16(s2u(base + 2*KVE) + so, Gh + gk + NKH*HD);
            cpa16(s2u(base + 3*KVE) + so, Gl + gk + NKH*HD);
        }
        if (tid < 32)      cpa4(s2u(poskA + db*32 + tid),      pos + b*TT + s0g + tid);
        else if (tid < 64) cpa4(s2u(segkA + db*32 + (tid-32)), seg + b*TT + s0g + (tid-32));
        cp_commit();
    };

    // start K/V pipeline immediately, overlap with Q load
    issue_kv(0, 0);

    // Q tile -> smem (normal loads)
#pragma unroll
    for (int i=0;i<8;i++){
        int f = tid + i*128; int r = f>>4; int h8 = (f&15)*8;
        size_t go = (size_t)(b*TT + q0 + r)*QKV_LD + n*HD + h8;
        *(uint4*)(Qh_s + r*FSTR + h8) = *(const uint4*)(Gh + go);
        *(uint4*)(Ql_s + r*FSTR + h8) = *(const uint4*)(Gl + go);
    }
    if (tid<64){ posq[tid]=pos[b*TT+q0+tid]; segq[tid]=seg[b*TT+q0+tid]; }
    __syncthreads();

    const int ar = lane&15, ac8 = (lane>>4)*8;
    const int br = ((lane>>4)<<3) + (lane&7), bc8 = lane&8;
    const int cb = 2*(lane&3);

    // Q fragments -> registers (used for every tile; Q smem not touched again)
    uint32_t qfh[8][4], qfl[8][4];
    {
        const uint32_t qh_s = s2u(Qh_s), ql_s = s2u(Ql_s);
#pragma unroll
        for (int ks=0; ks<8; ks++){
            uint32_t aoff = (uint32_t)((warp*16 + ar)*FSTR + ks*16 + ac8)*2;
            ldm4(qfh[ks], qh_s + aoff);
            ldm4(qfl[ks], ql_s + aoff);
        }
    }

    const int rql = warp*16 + (lane>>2);
    const int pq0=posq[rql], sq0=segq[rql], pq1=posq[rql+8], sq1=segq[rql+8];

    float m0r=NEGI, m1r=NEGI, l0=0.f, l1=0.f;
    float oacc[16][4];
#pragma unroll
    for (int i=0;i<16;i++)
#pragma unroll
        for (int j=0;j<4;j++) oacc[i][j]=0.f;

    const int ntk = 2*qt + 2;
    int db = 0;
    for (int kt=0; kt<ntk; kt++){
        if (kt+1 < ntk){
            issue_kv(kt+1, db^1);
            asm volatile("cp.async.wait_group 1;" ::: "memory");
        } else {
            asm volatile("cp.async.wait_group 0;" ::: "memory");
        }
        __syncthreads();

        bf16* base = KVb + db*4*KVE;
        const uint32_t kh_s = s2u(base),          kl_s = s2u(base + KVE);
        const uint32_t vh_s = s2u(base + 2*KVE),  vl_s = s2u(base + 3*KVE);
        const int* posk = poskA + db*32;
        const int* segk = segkA + db*32;

        float sacc[4][4];
#pragma unroll
        for (int i=0;i<4;i++)
#pragma unroll
            for (int j=0;j<4;j++) sacc[i][j]=0.f;

        // ---- S = Q K^T (16 q-rows x 32 k-cols per warp) ----
#pragma unroll
        for (int ks=0; ks<8; ks++){
#pragma unroll
            for (int ntp=0; ntp<2; ntp++){
                uint32_t bh[4], bl[4];
                uint32_t boff = (uint32_t)((ntp*16 + br)*FSTR + ks*16 + bc8)*2;
                ldm4(bh, kh_s + boff);
                ldm4(bl, kl_s + boff);
#pragma unroll
                for (int sb=0; sb<2; sb++){
                    float* c = sacc[ntp*2+sb];
                    mma16816(c, qfh[ks], bh + sb*2);
                    mma16816(c, qfh[ks], bl + sb*2);
                    mma16816(c, qfl[ks], bh + sb*2);
                }
            }
        }

        // ---- scale + mask + online softmax ----
        float t0=NEGI, t1=NEGI;
#pragma unroll
        for (int nt=0; nt<4; nt++){
            int c0 = nt*8 + cb;
            int pk0=posk[c0], sk0=segk[c0], pk1=posk[c0+1], sk1=segk[c0+1];
            float v00 = (pk0<=pq0 && sk0==sq0) ? sacc[nt][0]*SCALEV : MASKV;
            float v01 = (pk1<=pq0 && sk1==sq0) ? sacc[nt][1]*SCALEV : MASKV;
            float v10 = (pk0<=pq1 && sk0==sq1) ? sacc[nt][2]*SCALEV : MASKV;
            float v11 = (pk1<=pq1 && sk1==sq1) ? sacc[nt][3]*SCALEV : MASKV;
            sacc[nt][0]=v00; sacc[nt][1]=v01; sacc[nt][2]=v10; sacc[nt][3]=v11;
            t0 = fmaxf(t0, fmaxf(v00,v01));
            t1 = fmaxf(t1, fmaxf(v10,v11));
        }
        t0 = fmaxf(t0, __shfl_xor_sync(0xFFFFFFFFu, t0, 1));
        t0 = fmaxf(t0, __shfl_xor_sync(0xFFFFFFFFu, t0, 2));
        t1 = fmaxf(t1, __shfl_xor_sync(0xFFFFFFFFu, t1, 1));
        t1 = fmaxf(t1, __shfl_xor_sync(0xFFFFFFFFu, t1, 2));
        float nm0 = fmaxf(m0r, t0), nm1 = fmaxf(m1r, t1);
        float a0 = __expf(m0r-nm0), a1 = __expf(m1r-nm1);
        float rs0=0.f, rs1=0.f;
#pragma unroll
        for (int nt=0; nt<4; nt++){
            float p00=__expf(sacc[nt][0]-nm0), p01=__expf(sacc[nt][1]-nm0);
            float p10=__expf(sacc[nt][2]-nm1), p11=__expf(sacc[nt][3]-nm1);
            sacc[nt][0]=p00; sacc[nt][1]=p01; sacc[nt][2]=p10; sacc[nt][3]=p11;
            rs0 += p00+p01; rs1 += p10+p11;
        }
        rs0 += __shfl_xor_sync(0xFFFFFFFFu, rs0, 1);
        rs0 += __shfl_xor_sync(0xFFFFFFFFu, rs0, 2);
        rs1 += __shfl_xor_sync(0xFFFFFFFFu, rs1, 1);
        rs1 += __shfl_xor_sync(0xFFFFFFFFu, rs1, 2);
        l0 = l0*a0 + rs0; l1 = l1*a1 + rs1;
        m0r = nm0; m1r = nm1;
#pragma unroll
        for (int nt=0; nt<16; nt++){
            oacc[nt][0]*=a0; oacc[nt][1]*=a0; oacc[nt][2]*=a1; oacc[nt][3]*=a1;
        }

        // ---- O += P V (P 16x32, V 32x128) ----
#pragma unroll
        for (int ks=0; ks<2; ks++){
            uint32_t pah[4], pal[4];
            hl_pack(sacc[2*ks][0],   sacc[2*ks][1],   pah[0], pal[0]);
            hl_pack(sacc[2*ks][2],   sacc[2*ks][3],   pah[1], pal[1]);
            hl_pack(sacc[2*ks+1][0], sacc[2*ks+1][1], pah[2], pal[2]);
            hl_pack(sacc[2*ks+1][2], sacc[2*ks+1][3], pah[3], pal[3]);
#pragma unroll
            for (int ntp=0; ntp<8; ntp++){
                uint32_t bh[4], bl[4];
                uint32_t off = (uint32_t)((ks*16 + ar)*FSTR + ntp*16 + ac8)*2;
                ldm4t(bh, vh_s + off);
                ldm4t(bl, vl_s + off);
#pragma unroll
                for (int sb=0; sb<2; sb++){
                    float* c = oacc[ntp*2+sb];
                    mma16816(c, pah, bh + sb*2);
                    mma16816(c, pah, bl + sb*2);
                    mma16816(c, pal, bh + sb*2);
                }
            }
        }
        __syncthreads();
        db ^= 1;
    }

    // ---- epilogue ----
    float il0 = 1.f/l0, il1 = 1.f/l1;
#pragma unroll
    for (int nt=0; nt<16; nt++){
        int hcol = nt*8 + cb;
        size_t o0 = (size_t)(b*TT + q0 + warp*16 + (lane>>2))*ATT_LD + n*HD + hcol;
        uint32_t h, l;
        hl_pack(oacc[nt][0]*il0, oacc[nt][1]*il0, h, l);
        *(uint32_t*)(atth + o0) = h; *(uint32_t*)(attl + o0) = l;
        hl_pack(oacc[nt][2]*il1, oacc[nt][3]*il1, h, l);
        *(uint32_t*)(atth + o0 + 8*ATT_LD) = h; *(uint32_t*)(attl + o0 + 8*ATT_LD) = l;
    }
}

// ---------------------------------------------------------------------------
// Launch
// ---------------------------------------------------------------------------
extern "C" void kernel_launch(void* const* d_in, const int* in_sizes, int n_in,
                              void* d_out, int out_size)
{
    const float* x       = (const float*)d_in[0];
    const int*   seg     = (const int*)d_in[1];
    const float* wq      = (const float*)d_in[2];
    const float* wk      = (const float*)d_in[3];
    const float* wv      = (const float*)d_in[4];
    const float* wo      = (const float*)d_in[5];
    const float* q_scale = (const float*)d_in[6];
    const float* k_scale = (const float*)d_in[7];
    float* out           = (float*)d_out;

    float* qkv; cudaGetSymbolAddress((void**)&qkv, g_qkv);
    bf16 *xh, *xl, *wh, *wl, *qh, *ql, *ah, *al, *oh, *ol;
    cudaGetSymbolAddress((void**)&xh, g_xh); cudaGetSymbolAddress((void**)&xl, g_xl);
    cudaGetSymbolAddress((void**)&wh, g_wh); cudaGetSymbolAddress((void**)&wl, g_wl);
    cudaGetSymbolAddress((void**)&qh, g_qh); cudaGetSymbolAddress((void**)&ql, g_ql);
    cudaGetSymbolAddress((void**)&ah, g_ah); cudaGetSymbolAddress((void**)&al, g_al);
    cudaGetSymbolAddress((void**)&oh, g_oh); cudaGetSymbolAddress((void**)&ol, g_ol);
    float2* rope; cudaGetSymbolAddress((void**)&rope, g_rope);
    int* pos;     cudaGetSymbolAddress((void**)&pos, g_pos);

    cudaFuncSetAttribute(gemm3_kernel, cudaFuncAttributeMaxDynamicSharedMemorySize, GEMM_SMEM);
    cudaFuncSetAttribute(flash3_kernel, cudaFuncAttributeMaxDynamicSharedMemorySize, FLASH_SMEM);

    // 1) positions + rope table
    pos_kernel<<<TB, 256>>>(seg, pos);
    rope_kernel<<<(BT*64)/256, 256>>>(pos, rope);

    // 2) one combined split for x + all weights
    split_all_kernel<<<4096, 256>>>(x, wq, wk, wv, wo, xh, xl, wh, wl, oh, ol);

    // 3) QKV projection (bf16x3 tensor-core GEMM) -> fp32 qkv
    {
        dim3 g(QKV_LD/128, BT/128);
        gemm3_kernel<<<g, 256, GEMM_SMEM>>>(xh, xl, TD, wh, wl, QKV_LD, qkv, QKV_LD, TD);
    }

    // 4) RMSNorm + RoPE + hi/lo split -> qh/ql (all 32 head slots, v = split only)
    {
        dim3 g(BT, NQH + NKH + NKH);
        normrope_split_kernel<<<g, HD>>>(qkv, rope, q_scale, k_scale, qh, ql);
    }

    // 5) flash attention (Bk=32 cp.async pipeline, Q in registers)
    {
        dim3 g(TT/64, NQH, TB);
        flash3_kernel<<<g, 128, FLASH_SMEM>>>(qh, ql, pos, seg, ah, al);
    }

    // 6) output projection
    {
        dim3 g(TD/128, BT/128);
        gemm3_kernel<<<g, 256, GEMM_SMEM>>>(ah, al, ATT_LD, oh, ol, TD, out, TD, ATT_LD);
    }
}

// round 15
// speedup vs baseline: 1.1119x; 1.0306x over previous
#include <cuda_runtime.h>
#include <cuda_bf16.h>
#include <math.h>
#include <stdint.h>

#define TB 2
#define TT 2048
#define TD 1024
#define NQH 16
#define NKH 8
#define HD 128
#define BT (TB*TT)          // 4096
#define QKV_LD 4096
#define ATT_LD 2048
#define EPSV 1e-6f
#define SCALEV 0.08838834764831845f
#define LOG2_THETA 19.9315685693241740f
#define MASKV (-3.0e38f)
#define NEGI (-1e30f)

typedef __nv_bfloat16 bf16;
typedef __nv_bfloat162 bf162;

// Scratch (device globals; no runtime allocation)
__device__ float g_qkv[(size_t)BT*QKV_LD];   // 64MB fp32 qkv
__device__ bf16 g_xh[(size_t)BT*TD],     g_xl[(size_t)BT*TD];
__device__ bf16 g_wh[(size_t)TD*QKV_LD], g_wl[(size_t)TD*QKV_LD];
__device__ bf16 g_qh[(size_t)BT*QKV_LD], g_ql[(size_t)BT*QKV_LD];
__device__ bf16 g_ah[(size_t)BT*ATT_LD], g_al[(size_t)BT*ATT_LD];
__device__ bf16 g_oh[(size_t)ATT_LD*TD], g_ol[(size_t)ATT_LD*TD];
__device__ float2 g_rope[(size_t)BT*64];
__device__ int  g_pos[BT];

// ---------------------------------------------------------------------------
// helpers
// ---------------------------------------------------------------------------
__device__ __forceinline__ uint32_t s2u(const void* p){
    return (uint32_t)__cvta_generic_to_shared(p);
}
__device__ __forceinline__ void ldm4(uint32_t* r, uint32_t a){
    asm volatile("ldmatrix.sync.aligned.m8n8.x4.shared.b16 {%0,%1,%2,%3}, [%4];"
        : "=r"(r[0]),"=r"(r[1]),"=r"(r[2]),"=r"(r[3]) : "r"(a));
}
__device__ __forceinline__ void ldm4t(uint32_t* r, uint32_t a){
    asm volatile("ldmatrix.sync.aligned.m8n8.x4.trans.shared.b16 {%0,%1,%2,%3}, [%4];"
        : "=r"(r[0]),"=r"(r[1]),"=r"(r[2]),"=r"(r[3]) : "r"(a));
}
__device__ __forceinline__ void mma16816(float* c, const uint32_t* a, const uint32_t* b){
    asm volatile("mma.sync.aligned.m16n8k16.row.col.f32.bf16.bf16.f32 "
        "{%0,%1,%2,%3}, {%4,%5,%6,%7}, {%8,%9}, {%0,%1,%2,%3};"
        : "+f"(c[0]),"+f"(c[1]),"+f"(c[2]),"+f"(c[3])
        : "r"(a[0]),"r"(a[1]),"r"(a[2]),"r"(a[3]),"r"(b[0]),"r"(b[1]));
}
__device__ __forceinline__ void hl_pack(float x, float y, uint32_t& h, uint32_t& l){
    bf16 hx = __float2bfloat16(x), hy = __float2bfloat16(y);
    bf162 th = __halves2bfloat162(hx, hy);
    h = *reinterpret_cast<uint32_t*>(&th);
    bf162 tl = __floats2bfloat162_rn(x - __bfloat162float(hx), y - __bfloat162float(hy));
    l = *reinterpret_cast<uint32_t*>(&tl);
}
__device__ __forceinline__ void hl_split1(float x, bf16& h, bf16& l){
    h = __float2bfloat16(x);
    l = __float2bfloat16(x - __bfloat162float(h));
}
__device__ __forceinline__ void cpa16(uint32_t s, const void* g){
    asm volatile("cp.async.cg.shared.global [%0], [%1], 16;" :: "r"(s), "l"(g) : "memory");
}
__device__ __forceinline__ void cpa4(uint32_t s, const void* g){
    asm volatile("cp.async.ca.shared.global [%0], [%1], 4;" :: "r"(s), "l"(g) : "memory");
}
__device__ __forceinline__ void cp_commit(){
    asm volatile("cp.async.commit_group;" ::: "memory");
}

// ---------------------------------------------------------------------------
// Kernel: positions from segment ids
// ---------------------------------------------------------------------------
__global__ void pos_kernel(const int* __restrict__ seg, int* __restrict__ pos) {
    const int b = blockIdx.x;
    const int tid = threadIdx.x;
    __shared__ int red[256];
    int mx = -2147483647 - 1;
    for (int t = tid; t < TT; t += 256) mx = max(mx, seg[b*TT + t]);
    red[tid] = mx; __syncthreads();
    for (int s = 128; s > 0; s >>= 1) {
        if (tid < s) red[tid] = max(red[tid], red[tid + s]);
        __syncthreads();
    }
    const int gmax = red[0];
    __syncthreads();
    int idx = TT;
    for (int t = tid; t < TT; t += 256)
        if (seg[b*TT + t] == gmax && t < idx) idx = t;
    red[tid] = idx; __syncthreads();
    for (int s = 128; s > 0; s >>= 1) {
        if (tid < s) red[tid] = min(red[tid], red[tid + s]);
        __syncthreads();
    }
    const int off = red[0];
    for (int t = tid; t < TT; t += 256) {
        int sv = seg[b*TT + t];
        pos[b*TT + t] = (sv != 0) ? (t - off) : (1 << 30);
    }
}

// ---------------------------------------------------------------------------
// Kernel: rope table  rope[bt][j] = (sin, cos)(pos[bt] * theta^-(j/64))
// ---------------------------------------------------------------------------
__global__ void rope_kernel(const int* __restrict__ pos, float2* __restrict__ rope){
    int idx = blockIdx.x*blockDim.x + threadIdx.x;   // BT*64 total
    int bt = idx >> 6, j = idx & 63;
    float inv_freq = exp2f(-(float)j * (LOG2_THETA / 64.f));
    float ang = (float)pos[bt] * inv_freq;
    float s, c;
    sincosf(ang, &s, &c);
    rope[idx] = make_float2(s, c);
}

// ---------------------------------------------------------------------------
// Kernel: combined hi/lo split for x, wq, wk, wv, wo (one launch)
// ---------------------------------------------------------------------------
#define XG   1048576                 // 4096*1024/4
#define WQG  524288                  // 1024*2048/4
#define WKG  262144                  // 1024*1024/4
#define WVG  262144
#define WOG  524288                  // 2048*1024/4
#define TOTG (XG + WQG + WKG + WVG + WOG)

__device__ __forceinline__ void seg_split(const float* __restrict__ src,
                                          bf16* __restrict__ dh, bf16* __restrict__ dl,
                                          int g, int gpr, int sld, int dld, int doff)
{
    int r = g / gpr;
    int c = (g - r*gpr) * 4;
    float4 v = *(const float4*)&src[(size_t)r*sld + c];
    bf16 h0,h1,h2,h3,l0,l1,l2,l3;
    hl_split1(v.x,h0,l0); hl_split1(v.y,h1,l1);
    hl_split1(v.z,h2,l2); hl_split1(v.w,h3,l3);
    size_t o = (size_t)r*dld + doff + c;
    *(bf162*)&dh[o]   = __halves2bfloat162(h0,h1);
    *(bf162*)&dh[o+2] = __halves2bfloat162(h2,h3);
    *(bf162*)&dl[o]   = __halves2bfloat162(l0,l1);
    *(bf162*)&dl[o+2] = __halves2bfloat162(l2,l3);
}

__global__ void split_all_kernel(const float* __restrict__ x,
                                 const float* __restrict__ wq,
                                 const float* __restrict__ wk,
                                 const float* __restrict__ wv,
                                 const float* __restrict__ wo,
                                 bf16* __restrict__ xh, bf16* __restrict__ xl,
                                 bf16* __restrict__ wh, bf16* __restrict__ wl,
                                 bf16* __restrict__ oh, bf16* __restrict__ ol)
{
    for (int i = blockIdx.x*blockDim.x + threadIdx.x; i < TOTG; i += gridDim.x*blockDim.x) {
        if (i < XG) {
            seg_split(x, xh, xl, i, TD/4, TD, TD, 0);
        } else if (i < XG + WQG) {
            seg_split(wq, wh, wl, i - XG, (NQH*HD)/4, NQH*HD, QKV_LD, 0);
        } else if (i < XG + WQG + WKG) {
            seg_split(wk, wh, wl, i - XG - WQG, (NKH*HD)/4, NKH*HD, QKV_LD, NQH*HD);
        } else if (i < XG + WQG + WKG + WVG) {
            seg_split(wv, wh, wl, i - XG - WQG - WKG, (NKH*HD)/4, NKH*HD, QKV_LD, NQH*HD + NKH*HD);
        } else {
            seg_split(wo, oh, ol, i - XG - WQG - WKG - WVG, TD/4, TD, TD, 0);
        }
    }
}

// ---------------------------------------------------------------------------
// Kernel: RMSNorm + RoPE + hi/lo split, fp32 qkv -> qh/ql (all 32 head slots)
// ---------------------------------------------------------------------------
__global__ void normrope_split_kernel(const float* __restrict__ qkv,
                                      const float2* __restrict__ rope,
                                      const float* __restrict__ q_scale,
                                      const float* __restrict__ k_scale,
                                      bf16* __restrict__ dh, bf16* __restrict__ dl)
{
    __shared__ float wsum[4];
    __shared__ float buf[HD];

    const int bt = blockIdx.x;
    const int s  = blockIdx.y;
    const int h  = threadIdx.x;
    const float* base = qkv + (size_t)bt*QKV_LD + (size_t)s*HD;

    float v = base[h];
    float out;
    if (s < NQH + NKH) {
        float ss = v * v;
#pragma unroll
        for (int d = 16; d > 0; d >>= 1) ss += __shfl_xor_sync(0xFFFFFFFFu, ss, d);
        const int lane = h & 31, wid = h >> 5;
        if (lane == 0) wsum[wid] = ss;
        __syncthreads();
        float total = wsum[0] + wsum[1] + wsum[2] + wsum[3];
        float rinv = rsqrtf(total * (1.0f / HD) + EPSV);
        const float* sc = (s < NQH) ? q_scale : k_scale;
        float nv = sc[h] * v * rinv;
        buf[h] = nv;
        __syncthreads();
        const int f = h & 63;
        float2 t = rope[(size_t)bt*64 + f];
        float x1 = buf[f], x2 = buf[f + 64];
        out = (h < 64) ? (x1*t.y - x2*t.x) : (x2*t.y + x1*t.x);
    } else {
        out = v;
    }
    bf16 hh, ll;
    hl_split1(out, hh, ll);
    size_t o = (size_t)bt*QKV_LD + (size_t)s*HD + h;
    dh[o] = hh;
    dl[o] = ll;
}

// ---------------------------------------------------------------------------
// bf16x3 GEMM v2: cp.async 2-stage pipeline, 2 CTAs/SM target
// 128x128 block, 8 warps, K-step 32
// ---------------------------------------------------------------------------
#define GA_STR 40
#define GB_STR 136
#define G_ASZ (128*GA_STR)
#define G_BSZ (32*GB_STR)
#define G_BUF (2*G_ASZ + 2*G_BSZ)
#define GEMM_SMEM (2*G_BUF*2)

__global__ __launch_bounds__(256,2)
void gemm3_kernel(const bf16* __restrict__ Ah, const bf16* __restrict__ Al, int lda,
                  const bf16* __restrict__ Bh, const bf16* __restrict__ Bl, int ldb,
                  float* __restrict__ C, int ldc, int Kd)
{
    extern __shared__ bf16 sm[];
    const int tid = threadIdx.x, lane = tid&31, warp = tid>>5;
    const int wm = warp&1, wn = warp>>1;
    const int m0 = blockIdx.y*128, n0 = blockIdx.x*128;

    float acc[4][4][4];
#pragma unroll
    for (int i=0;i<4;i++)
#pragma unroll
        for (int j=0;j<4;j++)
#pragma unroll
            for (int q=0;q<4;q++) acc[i][j][q]=0.f;

    // 2-stage cp.async pipeline: per stage each thread moves
    // A: 2x16B (h) + 2x16B (l), B: 2x16B (h) + 2x16B (l)
    auto issue = [&](int t){
        const int k0 = t << 5;
        bf16* base = sm + (t&1)*G_BUF;
        bf16* sAh = base;
        bf16* sAl = base + G_ASZ;
        bf16* sBh = base + 2*G_ASZ;
        bf16* sBl = base + 2*G_ASZ + G_BSZ;
#pragma unroll
        for (int i=0;i<2;i++){
            int f = tid + i*256;
            int r = f>>2, k8 = (f&3)*8;
            size_t ao = (size_t)(m0+r)*lda + k0 + k8;
            cpa16(s2u(sAh + r*GA_STR + k8), Ah + ao);
            cpa16(s2u(sAl + r*GA_STR + k8), Al + ao);
            int kr = f>>4, n8 = (f&15)*8;
            size_t bo = (size_t)(k0+kr)*ldb + n0 + n8;
            cpa16(s2u(sBh + kr*GB_STR + n8), Bh + bo);
            cpa16(s2u(sBl + kr*GB_STR + n8), Bl + bo);
        }
        cp_commit();
    };

    const int nk = Kd >> 5;
    issue(0);
    const int ar = lane&15, ac8 = (lane>>4)*8;
    for (int t=0; t<nk; t++){
        if (t+1 < nk){
            issue(t+1);
            asm volatile("cp.async.wait_group 1;" ::: "memory");
        } else {
            asm volatile("cp.async.wait_group 0;" ::: "memory");
        }
        __syncthreads();

        bf16* base = sm + (t&1)*G_BUF;
        uint32_t ash = s2u(base), asl = s2u(base+G_ASZ);
        uint32_t bsh = s2u(base+2*G_ASZ), bsl = s2u(base+2*G_ASZ+G_BSZ);
#pragma unroll
        for (int ks=0; ks<32; ks+=16){
            uint32_t ah[4][4], al[4][4];
#pragma unroll
            for (int mt=0; mt<4; mt++){
                uint32_t off = (uint32_t)((wm*64 + mt*16 + ar)*GA_STR + ks + ac8)*2;
                ldm4(ah[mt], ash + off);
                ldm4(al[mt], asl + off);
            }
#pragma unroll
            for (int ntp=0; ntp<2; ntp++){
                uint32_t bh[4], bl[4];
                uint32_t off = (uint32_t)((ks + ar)*GB_STR + wn*32 + ntp*16 + ac8)*2;
                ldm4t(bh, bsh + off);
                ldm4t(bl, bsl + off);
#pragma unroll
                for (int mt=0; mt<4; mt++){
#pragma unroll
                    for (int sb=0; sb<2; sb++){
                        float* c = acc[mt][ntp*2+sb];
                        mma16816(c, ah[mt], bh + sb*2);
                        mma16816(c, ah[mt], bl + sb*2);
                        mma16816(c, al[mt], bh + sb*2);
                    }
                }
            }
        }
        __syncthreads();   // compute done before buffer reuse at t+2
    }
#pragma unroll
    for (int mt=0; mt<4; mt++){
        int r = m0 + wm*64 + mt*16 + (lane>>2);
#pragma unroll
        for (int nt=0; nt<4; nt++){
            int cc = n0 + wn*32 + nt*8 + 2*(lane&3);
            *(float2*)&C[(size_t)r*ldc + cc]     = make_float2(acc[mt][nt][0], acc[mt][nt][1]);
            *(float2*)&C[(size_t)(r+8)*ldc + cc] = make_float2(acc[mt][nt][2], acc[mt][nt][3]);
        }
    }
}

// ---------------------------------------------------------------------------
// Kernel: flash attention, Bq=64, Bk=32, 128 threads, cp.async double-buffered
// K/V, Q fragments register-resident. grid (T/64, NQH, B)  [proven R13]
// ---------------------------------------------------------------------------
#define FKT 32
#define FSTR 136
#define KVE (FKT*FSTR)
#define FLASH_SMEM ((2*64*FSTR + 8*KVE)*2 + 256*4)

__global__ __launch_bounds__(128)
void flash3_kernel(const bf16* __restrict__ Gh, const bf16* __restrict__ Gl,
                   const int* __restrict__ pos, const int* __restrict__ seg,
                   bf16* __restrict__ atth, bf16* __restrict__ attl)
{
    extern __shared__ bf16 fsm[];
    bf16* Qh_s = fsm;                  // 64 x FSTR
    bf16* Ql_s = Qh_s + 64*FSTR;
    bf16* KVb  = Ql_s + 64*FSTR;       // [2][Kh,Kl,Vh,Vl] x KVE
    int* posq  = (int*)(KVb + 8*KVE);  // 64
    int* segq  = posq + 64;
    int* poskA = segq + 64;            // [2][32]
    int* segkA = poskA + 64;

    const int tid=threadIdx.x, lane=tid&31, warp=tid>>5;
    const int qt=blockIdx.x, n=blockIdx.y, b=blockIdx.z;
    const int kh = n>>1, q0 = qt*64;

    auto issue_kv = [&](int kt, int db){
        bf16* base = KVb + db*4*KVE;
        const int s0g = kt*FKT;
#pragma unroll
        for (int i=0;i<4;i++){
            int f = tid + i*128;                  // 0..511
            int r = f>>4, c8 = (f&15)*8;          // row 0..31, chunk 0..15
            size_t gk = (size_t)(b*TT + s0g + r)*QKV_LD + NQH*HD + kh*HD + c8;
            uint32_t so = (uint32_t)(r*FSTR + c8)*2;
            cpa16(s2u(base) + so,         Gh + gk);
            cpa16(s2u(base + KVE) + so,   Gl + gk);
            cpa16(s2u(base + 2*KVE) + so, Gh + gk + NKH*HD);
            cpa16(s2u(base + 3*KVE) + so, Gl + gk + NKH*HD);
        }
        if (tid < 32)      cpa4(s2u(poskA + db*32 + tid),      pos + b*TT + s0g + tid);
        else if (tid < 64) cpa4(s2u(segkA + db*32 + (tid-32)), seg + b*TT + s0g + (tid-32));
        cp_commit();
    };

    // start K/V pipeline immediately, overlap with Q load
    issue_kv(0, 0);

    // Q tile -> smem (normal loads)
#pragma unroll
    for (int i=0;i<8;i++){
        int f = tid + i*128; int r = f>>4; int h8 = (f&15)*8;
        size_t go = (size_t)(b*TT + q0 + r)*QKV_LD + n*HD + h8;
        *(uint4*)(Qh_s + r*FSTR + h8) = *(const uint4*)(Gh + go);
        *(uint4*)(Ql_s + r*FSTR + h8) = *(const uint4*)(Gl + go);
    }
    if (tid<64){ posq[tid]=pos[b*TT+q0+tid]; segq[tid]=seg[b*TT+q0+tid]; }
    __syncthreads();

    const int ar = lane&15, ac8 = (lane>>4)*8;
    const int br = ((lane>>4)<<3) + (lane&7), bc8 = lane&8;
    const int cb = 2*(lane&3);

    // Q fragments -> registers (used for every tile; Q smem not touched again)
    uint32_t qfh[8][4], qfl[8][4];
    {
        const uint32_t qh_s = s2u(Qh_s), ql_s = s2u(Ql_s);
#pragma unroll
        for (int ks=0; ks<8; ks++){
            uint32_t aoff = (uint32_t)((warp*16 + ar)*FSTR + ks*16 + ac8)*2;
            ldm4(qfh[ks], qh_s + aoff);
            ldm4(qfl[ks], ql_s + aoff);
        }
    }

    const int rql = warp*16 + (lane>>2);
    const int pq0=posq[rql], sq0=segq[rql], pq1=posq[rql+8], sq1=segq[rql+8];

    float m0r=NEGI, m1r=NEGI, l0=0.f, l1=0.f;
    float oacc[16][4];
#pragma unroll
    for (int i=0;i<16;i++)
#pragma unroll
        for (int j=0;j<4;j++) oacc[i][j]=0.f;

    const int ntk = 2*qt + 2;
    int db = 0;
    for (int kt=0; kt<ntk; kt++){
        if (kt+1 < ntk){
            issue_kv(kt+1, db^1);
            asm volatile("cp.async.wait_group 1;" ::: "memory");
        } else {
            asm volatile("cp.async.wait_group 0;" ::: "memory");
        }
        __syncthreads();

        bf16* base = KVb + db*4*KVE;
        const uint32_t kh_s = s2u(base),          kl_s = s2u(base + KVE);
        const uint32_t vh_s = s2u(base + 2*KVE),  vl_s = s2u(base + 3*KVE);
        const int* posk = poskA + db*32;
        const int* segk = segkA + db*32;

        float sacc[4][4];
#pragma unroll
        for (int i=0;i<4;i++)
#pragma unroll
            for (int j=0;j<4;j++) sacc[i][j]=0.f;

        // ---- S = Q K^T (16 q-rows x 32 k-cols per warp) ----
#pragma unroll
        for (int ks=0; ks<8; ks++){
#pragma unroll
            for (int ntp=0; ntp<2; ntp++){
                uint32_t bh[4], bl[4];
                uint32_t boff = (uint32_t)((ntp*16 + br)*FSTR + ks*16 + bc8)*2;
                ldm4(bh, kh_s + boff);
                ldm4(bl, kl_s + boff);
#pragma unroll
                for (int sb=0; sb<2; sb++){
                    float* c = sacc[ntp*2+sb];
                    mma16816(c, qfh[ks], bh + sb*2);
                    mma16816(c, qfh[ks], bl + sb*2);
                    mma16816(c, qfl[ks], bh + sb*2);
                }
            }
        }

        // ---- scale + mask + online softmax ----
        float t0=NEGI, t1=NEGI;
#pragma unroll
        for (int nt=0; nt<4; nt++){
            int c0 = nt*8 + cb;
            int pk0=posk[c0], sk0=segk[c0], pk1=posk[c0+1], sk1=segk[c0+1];
            float v00 = (pk0<=pq0 && sk0==sq0) ? sacc[nt][0]*SCALEV : MASKV;
            float v01 = (pk1<=pq0 && sk1==sq0) ? sacc[nt][1]*SCALEV : MASKV;
            float v10 = (pk0<=pq1 && sk0==sq1) ? sacc[nt][2]*SCALEV : MASKV;
            float v11 = (pk1<=pq1 && sk1==sq1) ? sacc[nt][3]*SCALEV : MASKV;
            sacc[nt][0]=v00; sacc[nt][1]=v01; sacc[nt][2]=v10; sacc[nt][3]=v11;
            t0 = fmaxf(t0, fmaxf(v00,v01));
            t1 = fmaxf(t1, fmaxf(v10,v11));
        }
        t0 = fmaxf(t0, __shfl_xor_sync(0xFFFFFFFFu, t0, 1));
        t0 = fmaxf(t0, __shfl_xor_sync(0xFFFFFFFFu, t0, 2));
        t1 = fmaxf(t1, __shfl_xor_sync(0xFFFFFFFFu, t1, 1));
        t1 = fmaxf(t1, __shfl_xor_sync(0xFFFFFFFFu, t1, 2));
        float nm0 = fmaxf(m0r, t0), nm1 = fmaxf(m1r, t1);
        float a0 = __expf(m0r-nm0), a1 = __expf(m1r-nm1);
        float rs0=0.f, rs1=0.f;
#pragma unroll
        for (int nt=0; nt<4; nt++){
            float p00=__expf(sacc[nt][0]-nm0), p01=__expf(sacc[nt][1]-nm0);
            float p10=__expf(sacc[nt][2]-nm1), p11=__expf(sacc[nt][3]-nm1);
            sacc[nt][0]=p00; sacc[nt][1]=p01; sacc[nt][2]=p10; sacc[nt][3]=p11;
            rs0 += p00+p01; rs1 += p10+p11;
        }
        rs0 += __shfl_xor_sync(0xFFFFFFFFu, rs0, 1);
        rs0 += __shfl_xor_sync(0xFFFFFFFFu, rs0, 2);
        rs1 += __shfl_xor_sync(0xFFFFFFFFu, rs1, 1);
        rs1 += __shfl_xor_sync(0xFFFFFFFFu, rs1, 2);
        l0 = l0*a0 + rs0; l1 = l1*a1 + rs1;
        m0r = nm0; m1r = nm1;
#pragma unroll
        for (int nt=0; nt<16; nt++){
            oacc[nt][0]*=a0; oacc[nt][1]*=a0; oacc[nt][2]*=a1; oacc[nt][3]*=a1;
        }

        // ---- O += P V (P 16x32, V 32x128) ----
#pragma unroll
        for (int ks=0; ks<2; ks++){
            uint32_t pah[4], pal[4];
            hl_pack(sacc[2*ks][0],   sacc[2*ks][1],   pah[0], pal[0]);
            hl_pack(sacc[2*ks][2],   sacc[2*ks][3],   pah[1], pal[1]);
            hl_pack(sacc[2*ks+1][0], sacc[2*ks+1][1], pah[2], pal[2]);
            hl_pack(sacc[2*ks+1][2], sacc[2*ks+1][3], pah[3], pal[3]);
#pragma unroll
            for (int ntp=0; ntp<8; ntp++){
                uint32_t bh[4], bl[4];
                uint32_t off = (uint32_t)((ks*16 + ar)*FSTR + ntp*16 + ac8)*2;
                ldm4t(bh, vh_s + off);
                ldm4t(bl, vl_s + off);
#pragma unroll
                for (int sb=0; sb<2; sb++){
                    float* c = oacc[ntp*2+sb];
                    mma16816(c, pah, bh + sb*2);
                    mma16816(c, pah, bl + sb*2);
                    mma16816(c, pal, bh + sb*2);
                }
            }
        }
        __syncthreads();
        db ^= 1;
    }

    // ---- epilogue ----
    float il0 = 1.f/l0, il1 = 1.f/l1;
#pragma unroll
    for (int nt=0; nt<16; nt++){
        int hcol = nt*8 + cb;
        size_t o0 = (size_t)(b*TT + q0 + warp*16 + (lane>>2))*ATT_LD + n*HD + hcol;
        uint32_t h, l;
        hl_pack(oacc[nt][0]*il0, oacc[nt][1]*il0, h, l);
        *(uint32_t*)(atth + o0) = h; *(uint32_t*)(attl + o0) = l;
        hl_pack(oacc[nt][2]*il1, oacc[nt][3]*il1, h, l);
        *(uint32_t*)(atth + o0 + 8*ATT_LD) = h; *(uint32_t*)(attl + o0 + 8*ATT_LD) = l;
    }
}

// ---------------------------------------------------------------------------
// Launch
// ---------------------------------------------------------------------------
extern "C" void kernel_launch(void* const* d_in, const int* in_sizes, int n_in,
                              void* d_out, int out_size)
{
    const float* x       = (const float*)d_in[0];
    const int*   seg     = (const int*)d_in[1];
    const float* wq      = (const float*)d_in[2];
    const float* wk      = (const float*)d_in[3];
    const float* wv      = (const float*)d_in[4];
    const float* wo      = (const float*)d_in[5];
    const float* q_scale = (const float*)d_in[6];
    const float* k_scale = (const float*)d_in[7];
    float* out           = (float*)d_out;

    float* qkv; cudaGetSymbolAddress((void**)&qkv, g_qkv);
    bf16 *xh, *xl, *wh, *wl, *qh, *ql, *ah, *al, *oh, *ol;
    cudaGetSymbolAddress((void**)&xh, g_xh); cudaGetSymbolAddress((void**)&xl, g_xl);
    cudaGetSymbolAddress((void**)&wh, g_wh); cudaGetSymbolAddress((void**)&wl, g_wl);
    cudaGetSymbolAddress((void**)&qh, g_qh); cudaGetSymbolAddress((void**)&ql, g_ql);
    cudaGetSymbolAddress((void**)&ah, g_ah); cudaGetSymbolAddress((void**)&al, g_al);
    cudaGetSymbolAddress((void**)&oh, g_oh); cudaGetSymbolAddress((void**)&ol, g_ol);
    float2* rope; cudaGetSymbolAddress((void**)&rope, g_rope);
    int* pos;     cudaGetSymbolAddress((void**)&pos, g_pos);

    cudaFuncSetAttribute(gemm3_kernel, cudaFuncAttributeMaxDynamicSharedMemorySize, GEMM_SMEM);
    cudaFuncSetAttribute(flash3_kernel, cudaFuncAttributeMaxDynamicSharedMemorySize, FLASH_SMEM);

    // 1) positions + rope table
    pos_kernel<<<TB, 256>>>(seg, pos);
    rope_kernel<<<(BT*64)/256, 256>>>(pos, rope);

    // 2) one combined split for x + all weights
    split_all_kernel<<<4096, 256>>>(x, wq, wk, wv, wo, xh, xl, wh, wl, oh, ol);

    // 3) QKV projection (bf16x3 tensor-core GEMM, cp.async) -> fp32 qkv
    {
        dim3 g(QKV_LD/128, BT/128);
        gemm3_kernel<<<g, 256, GEMM_SMEM>>>(xh, xl, TD, wh, wl, QKV_LD, qkv, QKV_LD, TD);
    }

    // 4) RMSNorm + RoPE + hi/lo split -> qh/ql (all 32 head slots, v = split only)
    {
        dim3 g(BT, NQH + NKH + NKH);
        normrope_split_kernel<<<g, HD>>>(qkv, rope, q_scale, k_scale, qh, ql);
    }

    // 5) flash attention (Bk=32 cp.async pipeline, Q in registers)
    {
        dim3 g(TT/64, NQH, TB);
        flash3_kernel<<<g, 128, FLASH_SMEM>>>(qh, ql, pos, seg, ah, al);
    }

    // 6) output projection
    {
        dim3 g(TD/128, BT/128);
        gemm3_kernel<<<g, 256, GEMM_SMEM>>>(ah, al, ATT_LD, oh, ol, TD, out, TD, ATT_LD);
    }
}